// round 9
// baseline (speedup 1.0000x reference)
#include <cuda_runtime.h>
#include <cuda_bf16.h>
#include <math.h>
#include <stdint.h>

// ---------------- problem constants ----------------
#define BATCH  32
#define HEADS  12
#define SEQ    512
#define LHALF  256
#define DMODEL 768
#define HH     384          // hidden per direction
#define G4     1536         // 4*HH gates
#define DIN    1536         // 2*DMODEL LSTM input
#define BH     384          // BATCH*HEADS
#define TT     6            // SLIDER
#define EPSV   1e-9f

// ---------------- device scratch (no allocs allowed) ----------------
__device__ int   g_master[BH * 2];
__device__ float g_gatesX[(size_t)BH * TT * 2 * G4];   // 2304 x 3072, gate-interleaved cols, bias folded
__device__ float g_c[(size_t)2 * BH * HH];
__device__ float g_compose[(size_t)BH * TT * DMODEL];
__device__ float g_lrep[(size_t)BATCH * DMODEL];

// bf16 split operands (weights gate-interleaved: row' = 4*j + gate)
__device__ __nv_bfloat16 g_slide_h[(size_t)BH * TT * DIN];
__device__ __nv_bfloat16 g_slide_l[(size_t)BH * TT * DIN];
__device__ __nv_bfloat16 g_wih_h[(size_t)2 * G4 * DIN];
__device__ __nv_bfloat16 g_wih_l[(size_t)2 * G4 * DIN];
__device__ __nv_bfloat16 g_whh_h[(size_t)2 * G4 * HH];
__device__ __nv_bfloat16 g_whh_l[(size_t)2 * G4 * HH];
__device__ __nv_bfloat16 g_hb_h[(size_t)2 * BH * HH];     // [dir][n][j]
__device__ __nv_bfloat16 g_hb_l[(size_t)2 * BH * HH];
__device__ float g_bias[2 * G4];                          // gate-interleaved

// ---------------- PTX helpers (baseline PTX only) ----------------
__device__ __forceinline__ uint32_t smem_u32(const void* p) {
    uint32_t a;
    asm("{ .reg .u64 t; cvta.to.shared.u64 t, %1; cvt.u32.u64 %0, t; }" : "=r"(a) : "l"(p));
    return a;
}

#define CP_ASYNC16(sm, gm) \
    asm volatile("cp.async.cg.shared.global [%0], [%1], 16;" :: "r"(sm), "l"(gm) : "memory")
#define CP_COMMIT() asm volatile("cp.async.commit_group;" ::: "memory")
#define CP_WAIT0()  asm volatile("cp.async.wait_group 0;" ::: "memory")
#define CP_WAIT1()  asm volatile("cp.async.wait_group 1;" ::: "memory")

#define LDSM_X4(r0, r1, r2, r3, addr) \
    asm volatile("ldmatrix.sync.aligned.m8n8.x4.shared.b16 {%0,%1,%2,%3}, [%4];" \
        : "=r"(r0), "=r"(r1), "=r"(r2), "=r"(r3) : "r"(addr))

#define MMA_BF16(c0, c1, c2, c3, a0, a1, a2, a3, b0, b1) \
    asm volatile("mma.sync.aligned.m16n8k16.row.col.f32.bf16.bf16.f32 " \
        "{%0,%1,%2,%3}, {%4,%5,%6,%7}, {%8,%9}, {%0,%1,%2,%3};" \
        : "+f"(c0), "+f"(c1), "+f"(c2), "+f"(c3) \
        : "r"(a0), "r"(a1), "r"(a2), "r"(a3), "r"(b0), "r"(b1))

// ---------------- helpers ----------------
__device__ __forceinline__ float sigf(float x) { return 1.0f / (1.0f + expf(-x)); }

__device__ __forceinline__ int window_start(int pos) {
    pos = min(max(pos, 1), LHALF - 2);
    int l = TT / 2;
    if (pos - TT / 2 <= 0) l = pos - 1;
    int r = TT - l;
    if (pos + r >= LHALF - 1) l = TT - (LHALF - pos - 2);
    return pos - l;
}

// ---------------- K1: masters ----------------
__global__ void masters_kernel(const float* __restrict__ att, const int* __restrict__ sents) {
    int bid  = blockIdx.x;
    int half = bid & 1;
    int bh   = bid >> 1;
    int b    = bh / HEADS;

    __shared__ unsigned char seps[LHALF];
    __shared__ float rowsum[LHALF];

    int tid = threadIdx.x;
    {
        int j = half * LHALF + tid;
        seps[tid] = (sents[b * SEQ + j] == 102) ? 1 : 0;
    }
    __syncthreads();

    const float* base = att + ((size_t)bh * SEQ + (size_t)half * LHALF) * SEQ + (size_t)half * LHALF;

    int warp = tid >> 5, lane = tid & 31;
    for (int row = warp; row < LHALF; row += 8) {
        const float4* rp4 = (const float4*)(base + (size_t)row * SEQ);
        float s = 0.0f;
        #pragma unroll
        for (int k = 0; k < 2; k++) {
            int j4 = lane + 32 * k;
            float4 v = __ldg(rp4 + j4);
            int j = j4 * 4;
            s += seps[j]     ? EPSV : v.x;
            s += seps[j + 1] ? EPSV : v.y;
            s += seps[j + 2] ? EPSV : v.z;
            s += seps[j + 3] ? EPSV : v.w;
        }
        #pragma unroll
        for (int off = 16; off > 0; off >>= 1)
            s += __shfl_down_sync(0xffffffffu, s, off);
        if (lane == 0) rowsum[row] = s;
    }
    __syncthreads();

    __shared__ float bv[LHALF];
    __shared__ int   bix[LHALF];
    bv[tid]  = rowsum[tid];
    bix[tid] = tid;
    __syncthreads();
    for (int off = 128; off > 0; off >>= 1) {
        if (tid < off) {
            float vo = bv[tid + off];
            int   io = bix[tid + off];
            if (vo > bv[tid] || (vo == bv[tid] && io < bix[tid])) { bv[tid] = vo; bix[tid] = io; }
        }
        __syncthreads();
    }
    if (tid == 0) g_master[bh * 2 + half] = bix[0];
}

// ---------------- K2: gather windows -> slide (bf16 hi/lo) ----------------
__global__ void build_slide(const float* __restrict__ logits, const int* __restrict__ mask) {
    int bh = blockIdx.x;
    int b  = bh / HEADS;
    __shared__ int sa, sb;
    if (threadIdx.x == 0) {
        sa = window_start(g_master[bh * 2 + 0]);
        sb = window_start(g_master[bh * 2 + 1]);
    }
    __syncthreads();

    for (int idx = threadIdx.x; idx < TT * DIN; idx += blockDim.x) {
        int t = idx / DIN, f = idx % DIN;
        float v;
        if (f < DMODEL) {
            int row = sa + t;
            v = (mask[b * SEQ + row] == 0) ? EPSV
                : logits[((size_t)b * SEQ + row) * DMODEL + f];
        } else {
            int row = LHALF + sb + t;
            v = (mask[b * SEQ + row] == 0) ? EPSV
                : logits[((size_t)b * SEQ + row) * DMODEL + (f - DMODEL)];
        }
        size_t off = (size_t)bh * (TT * DIN) + idx;
        __nv_bfloat16 hi = __float2bfloat16(v);
        g_slide_h[off] = hi;
        g_slide_l[off] = __float2bfloat16(v - __bfloat162float(hi));
    }
}

// ---------------- K3: fused prep (weight splits with gate interleave + bias) ----------------
// Output row within each direction block: row' = 4*j + gate, where src row = gate*HH + j.
#define NW ((size_t)G4 * DIN)    // 2359296
#define NH ((size_t)G4 * HH)     // 589824
#define PREP_TOTAL (2 * NW + 2 * NH + 2 * G4)

__global__ void prep_kernel(const float* __restrict__ wih_f, const float* __restrict__ wih_r,
                            const float* __restrict__ whh_f, const float* __restrict__ whh_r,
                            const float* __restrict__ bihf, const float* __restrict__ bhhf,
                            const float* __restrict__ bihr, const float* __restrict__ bhhr) {
    size_t i = (size_t)blockIdx.x * blockDim.x + threadIdx.x;
    if (i >= PREP_TOTAL) return;
    if (i < 2 * NW + 2 * NH) {
        const float* src;
        __nv_bfloat16 *dh, *dl;
        size_t off;
        int kdim;
        if (i < NW)               { src = wih_f; dh = g_wih_h;      dl = g_wih_l;      off = i;                kdim = DIN; }
        else if (i < 2 * NW)      { src = wih_r; dh = g_wih_h + NW; dl = g_wih_l + NW; off = i - NW;           kdim = DIN; }
        else if (i < 2 * NW + NH) { src = whh_f; dh = g_whh_h;      dl = g_whh_l;      off = i - 2 * NW;       kdim = HH;  }
        else                      { src = whh_r; dh = g_whh_h + NH; dl = g_whh_l + NH; off = i - 2 * NW - NH;  kdim = HH;  }
        size_t row = off / kdim, k = off % kdim;
        int gate = (int)(row / HH), j = (int)(row % HH);
        size_t drow = (size_t)(4 * j + gate);
        float x = src[off];
        __nv_bfloat16 hi = __float2bfloat16(x);
        dh[drow * kdim + k] = hi;
        dl[drow * kdim + k] = __float2bfloat16(x - __bfloat162float(hi));
    } else {
        size_t q = i - (2 * NW + 2 * NH);      // [0, 2*G4)
        int dir = (int)(q / G4);
        int r   = (int)(q % G4);
        int gate = r / HH, j = r % HH;
        float v = dir ? (bihr[r] + bhhr[r]) : (bihf[r] + bhhf[r]);
        g_bias[dir * G4 + 4 * j + gate] = v;
    }
}

// ---------------- GEMM core: 3-stage cp.async pipeline, bf16 3-product split ----------------
#define BK          64
#define CHUNK_BYTES 16384          // 128 rows x 128B (64 bf16)
#define BUF_BYTES   (4 * CHUNK_BYTES)
#define NSTAGE      3
#define GM_SMEM     (1024 + NSTAGE * BUF_BYTES)

__device__ __forceinline__ void gemm_core(
    const __nv_bfloat16* Ah, const __nv_bfloat16* Al,
    const __nv_bfloat16* Bh, const __nv_bfloat16* Bl,
    int bm, int bn, int K, int NC,
    char* smem_raw, uint32_t tiles_u,
    int tid, int lane, int wm, int wn,
    float acc[4][4][4])
{
    int Kd8 = K >> 3;
    const __nv_bfloat16* srcs[4] = {Ah, Al, Bh, Bl};
    int rows0[4] = {bm, bm, bn, bn};

    auto load_chunk = [&](int c, int buf) {
        int k0 = c * BK;
        uint32_t bufu = tiles_u + buf * BUF_BYTES;
        #pragma unroll
        for (int t4 = 0; t4 < 4; t4++) {
            const uint4* gp = (const uint4*)(srcs[t4] + (size_t)rows0[t4] * K + k0);
            uint32_t tb = bufu + t4 * CHUNK_BYTES;
            #pragma unroll
            for (int i = 0; i < 4; i++) {
                int u = tid + i * 256;
                int r = u >> 3, c16 = u & 7;
                const uint4* ga = gp + (size_t)r * Kd8 + c16;
                uint32_t off = (uint32_t)(r * 128 + c16 * 16);
                uint32_t sw = off ^ ((off >> 3) & 0x70);
                CP_ASYNC16(tb + sw, ga);
            }
        }
    };

    load_chunk(0, 0);
    CP_COMMIT();
    if (NC > 1) { load_chunk(1, 1); CP_COMMIT(); }

    for (int c = 0; c < NC; c++) {
        if (c + 1 < NC) CP_WAIT1(); else CP_WAIT0();
        __syncthreads();
        if (c + 2 < NC) { load_chunk(c + 2, (c + 2) % NSTAGE); CP_COMMIT(); }

        uint32_t base = tiles_u + (c % NSTAGE) * BUF_BYTES;
        uint32_t ah_base = base;
        uint32_t al_base = base + CHUNK_BYTES;
        uint32_t bh_base = base + 2 * CHUNK_BYTES;
        uint32_t bl_base = base + 3 * CHUNK_BYTES;

        #pragma unroll
        for (int ks = 0; ks < 4; ks++) {
            uint32_t a_h[4][4], a_l[4][4];
            #pragma unroll
            for (int mt = 0; mt < 4; mt++) {
                uint32_t r = wm + mt * 16 + (lane & 15);
                uint32_t coloff = ks * 32 + ((lane >> 4) & 1) * 16;
                uint32_t off = r * 128 + coloff;
                uint32_t sw = off ^ ((off >> 3) & 0x70);
                LDSM_X4(a_h[mt][0], a_h[mt][1], a_h[mt][2], a_h[mt][3], ah_base + sw);
                LDSM_X4(a_l[mt][0], a_l[mt][1], a_l[mt][2], a_l[mt][3], al_base + sw);
            }
            uint32_t b_h[4][2], b_l[4][2];
            #pragma unroll
            for (int h = 0; h < 2; h++) {
                uint32_t r = wn + h * 16 + (lane & 7) + ((lane >> 4) << 3);
                uint32_t coloff = ks * 32 + ((lane >> 3) & 1) * 16;
                uint32_t off = r * 128 + coloff;
                uint32_t sw = off ^ ((off >> 3) & 0x70);
                uint32_t r0, r1, r2, r3;
                LDSM_X4(r0, r1, r2, r3, bh_base + sw);
                b_h[2 * h][0] = r0; b_h[2 * h][1] = r1;
                b_h[2 * h + 1][0] = r2; b_h[2 * h + 1][1] = r3;
                LDSM_X4(r0, r1, r2, r3, bl_base + sw);
                b_l[2 * h][0] = r0; b_l[2 * h][1] = r1;
                b_l[2 * h + 1][0] = r2; b_l[2 * h + 1][1] = r3;
            }
            #pragma unroll
            for (int mt = 0; mt < 4; mt++)
                #pragma unroll
                for (int nt = 0; nt < 4; nt++)
                    MMA_BF16(acc[mt][nt][0], acc[mt][nt][1], acc[mt][nt][2], acc[mt][nt][3],
                             a_h[mt][0], a_h[mt][1], a_h[mt][2], a_h[mt][3],
                             b_h[nt][0], b_h[nt][1]);
            #pragma unroll
            for (int mt = 0; mt < 4; mt++)
                #pragma unroll
                for (int nt = 0; nt < 4; nt++)
                    MMA_BF16(acc[mt][nt][0], acc[mt][nt][1], acc[mt][nt][2], acc[mt][nt][3],
                             a_h[mt][0], a_h[mt][1], a_h[mt][2], a_h[mt][3],
                             b_l[nt][0], b_l[nt][1]);
            #pragma unroll
            for (int mt = 0; mt < 4; mt++)
                #pragma unroll
                for (int nt = 0; nt < 4; nt++)
                    MMA_BF16(acc[mt][nt][0], acc[mt][nt][1], acc[mt][nt][2], acc[mt][nt][3],
                             a_l[mt][0], a_l[mt][1], a_l[mt][2], a_l[mt][3],
                             b_h[nt][0], b_h[nt][1]);
        }
        __syncthreads();
    }
}

// ---------------- K4: input GEMM ----------------
__global__ __launch_bounds__(256, 1) void input_gemm_hmma() {
    extern __shared__ char smem_raw[];
    uint32_t smem_u = smem_u32(smem_raw);
    uint32_t tiles_u = (smem_u + 1023) & ~1023u;

    int tid = threadIdx.x, wid = tid >> 5, lane = tid & 31;
    int wm = (wid & 1) * 64, wn = (wid >> 1) * 32;
    int bm = blockIdx.y * 128;
    int bn = blockIdx.x * 128;

    float acc[4][4][4];
    #pragma unroll
    for (int i = 0; i < 4; i++)
        #pragma unroll
        for (int j = 0; j < 4; j++)
            #pragma unroll
            for (int q = 0; q < 4; q++) acc[i][j][q] = 0.0f;

    gemm_core(g_slide_h, g_slide_l, g_wih_h, g_wih_l,
              bm, bn, DIN, DIN / BK, smem_raw, tiles_u, tid, lane, wm, wn, acc);

    #pragma unroll
    for (int mt = 0; mt < 4; mt++) {
        #pragma unroll
        for (int nt = 0; nt < 4; nt++) {
            int row = bm + wm + mt * 16 + (lane >> 2);
            int col = bn + wn + nt * 8 + (lane & 3) * 2;
            float b0 = g_bias[col], b1 = g_bias[col + 1];
            float2 v0 = make_float2(acc[mt][nt][0] + b0, acc[mt][nt][1] + b1);
            float2 v1 = make_float2(acc[mt][nt][2] + b0, acc[mt][nt][3] + b1);
            *(float2*)(g_gatesX + (size_t)row * (2 * G4) + col) = v0;
            *(float2*)(g_gatesX + (size_t)(row + 8) * (2 * G4) + col) = v1;
        }
    }
}

// ---------------- K5: LSTM step 0 (no recurrent term; h0 = c0 = 0) ----------------
__global__ void lstm0_kernel() {
    int idx = blockIdx.x * blockDim.x + threadIdx.x;    // over 2*BH*HH
    if (idx >= 2 * BH * HH) return;
    int dir = idx / (BH * HH);
    int r   = idx % (BH * HH);
    int n   = r / HH;
    int j   = r % HH;
    int t   = dir ? (TT - 1) : 0;

    float4 gx = *(const float4*)(g_gatesX + ((size_t)(n * TT + t)) * (2 * G4)
                                 + (size_t)dir * G4 + 4 * j);
    float c = sigf(gx.x) * tanhf(gx.z);
    float h = sigf(gx.w) * tanhf(c);
    g_c[idx] = c;
    __nv_bfloat16 hi = __float2bfloat16(h);
    g_hb_h[idx] = hi;
    g_hb_l[idx] = __float2bfloat16(h - __bfloat162float(hi));
    g_compose[((size_t)n * TT + t) * DMODEL + dir * HH + j] = h;
}

// ---------------- K6: fused recurrent GEMM + LSTM pointwise (steps 1..5) ----------------
__global__ __launch_bounds__(256, 1) void fused_step_kernel(int s) {
    extern __shared__ char smem_raw[];
    uint32_t smem_u = smem_u32(smem_raw);
    uint32_t tiles_u = (smem_u + 1023) & ~1023u;

    int dir = blockIdx.z;
    const __nv_bfloat16* Ah = g_hb_h + (size_t)dir * BH * HH;
    const __nv_bfloat16* Al = g_hb_l + (size_t)dir * BH * HH;
    const __nv_bfloat16* Bh = g_whh_h + (size_t)dir * G4 * HH;
    const __nv_bfloat16* Bl = g_whh_l + (size_t)dir * G4 * HH;

    int tid = threadIdx.x, wid = tid >> 5, lane = tid & 31;
    int wm = (wid & 1) * 64, wn = (wid >> 1) * 32;
    int bm = blockIdx.y * 128;         // batch-row tile (BH=384 -> 3 tiles)
    int bn = blockIdx.x * 128;         // gate-col tile  (G4=1536 -> 12 tiles)

    float acc[4][4][4];
    #pragma unroll
    for (int i = 0; i < 4; i++)
        #pragma unroll
        for (int j = 0; j < 4; j++)
            #pragma unroll
            for (int q = 0; q < 4; q++) acc[i][j][q] = 0.0f;

    gemm_core(Ah, Al, Bh, Bl, bm, bn, HH, HH / BK,
              smem_raw, tiles_u, tid, lane, wm, wn, acc);

    // Epilogue: acc cols are gate-interleaved (col = 4*j_local + gate).
    // Lane quad holds col pairs (0,1),(2,3),(4,5),(6,7) of an 8-col nt tile:
    // even lanes (lane&1==0) hold gates (i,f); odd lanes hold gates (g,o) of the same j.
    int t = dir ? (TT - 1 - s) : s;
    int jq = ((lane & 3) >> 1);               // which of the 2 hidden units in this nt tile

    #pragma unroll
    for (int mt = 0; mt < 4; mt++) {
        #pragma unroll
        for (int nt = 0; nt < 4; nt++) {
            #pragma unroll
            for (int q = 0; q < 2; q++) {     // row halves: r0, r0+8
                float v0 = acc[mt][nt][2 * q];
                float v1 = acc[mt][nt][2 * q + 1];
                float p0 = __shfl_xor_sync(0xffffffffu, v0, 1);
                float p1 = __shfl_xor_sync(0xffffffffu, v1, 1);
                if ((lane & 1) == 0) {
                    int n = bm + wm + mt * 16 + (lane >> 2) + q * 8;
                    int j = (bn + wn + nt * 8) / 4 + jq;
                    float4 gx = *(const float4*)(g_gatesX + ((size_t)(n * TT + t)) * (2 * G4)
                                                 + (size_t)dir * G4 + 4 * j);
                    float gi = gx.x + v0;
                    float gf = gx.y + v1;
                    float gg = gx.z + p0;
                    float go = gx.w + p1;
                    int idx = dir * (BH * HH) + n * HH + j;
                    float c = sigf(gf) * g_c[idx] + sigf(gi) * tanhf(gg);
                    float h = sigf(go) * tanhf(c);
                    g_c[idx] = c;
                    __nv_bfloat16 hi2 = __float2bfloat16(h);
                    g_hb_h[idx] = hi2;
                    g_hb_l[idx] = __float2bfloat16(h - __bfloat162float(hi2));
                    g_compose[((size_t)n * TT + t) * DMODEL + dir * HH + j] = h;
                }
            }
        }
    }
}

// ---------------- K7: logits_rep ----------------
__global__ void logits_rep_kernel(const float* __restrict__ logits, const int* __restrict__ mask) {
    int b = blockIdx.x;
    int tid = threadIdx.x;

    __shared__ unsigned char repl[SEQ];
    for (int i = tid; i < SEQ; i += blockDim.x) repl[i] = 0;
    __syncthreads();
    if (tid < 2 * HEADS) {
        int h = tid >> 1, half = tid & 1;
        int st = window_start(g_master[(b * HEADS + h) * 2 + half]);
        int base = half * LHALF + st;
        for (int k = 0; k < TT; k++) repl[base + k] = 1;
    }
    __syncthreads();
    for (int sPos = tid; sPos < SEQ; sPos += blockDim.x)
        repl[sPos] = (repl[sPos] && mask[b * SEQ + sPos] == 0) ? 1 : 0;
    __syncthreads();

    for (int d = tid; d < DMODEL; d += blockDim.x) {
        float a0 = 0.f, a1 = 0.f, a2 = 0.f, a3 = 0.f;
        const float* lp = logits + (size_t)b * SEQ * DMODEL + d;
        for (int sPos = 0; sPos < SEQ; sPos += 4) {
            float v0 = __ldg(lp + (size_t)(sPos + 0) * DMODEL);
            float v1 = __ldg(lp + (size_t)(sPos + 1) * DMODEL);
            float v2 = __ldg(lp + (size_t)(sPos + 2) * DMODEL);
            float v3 = __ldg(lp + (size_t)(sPos + 3) * DMODEL);
            a0 += repl[sPos]     ? EPSV : v0;
            a1 += repl[sPos + 1] ? EPSV : v1;
            a2 += repl[sPos + 2] ? EPSV : v2;
            a3 += repl[sPos + 3] ? EPSV : v3;
        }
        g_lrep[(size_t)b * DMODEL + d] = (a0 + a1 + a2 + a3) * (1.0f / (float)SEQ);
    }
}

// ---------------- K8: final FC + softmax ----------------
__global__ void final_kernel(const float* __restrict__ fcw, const float* __restrict__ fcb,
                             float* __restrict__ out) {
    int b = blockIdx.x;
    int tid = threadIdx.x;
    const int NF = DMODEL * (HEADS + 1);
    float a0 = 0.0f, a1 = 0.0f;

    for (int j = tid; j < NF; j += 256) {
        float x;
        if (j < HEADS * DMODEL) {
            int h = j / DMODEL, d = j % DMODEL;
            int n = b * HEADS + h;
            const float* cp = g_compose + (size_t)n * TT * DMODEL + d;
            float s = 0.0f;
            #pragma unroll
            for (int t = 0; t < TT; t++) s += cp[(size_t)t * DMODEL];
            x = s * (1.0f / (float)TT);
        } else {
            x = g_lrep[(size_t)b * DMODEL + (j - HEADS * DMODEL)];
        }
        a0 += x * fcw[j];
        a1 += x * fcw[NF + j];
    }

    __shared__ float s0[256], s1[256];
    s0[tid] = a0; s1[tid] = a1;
    __syncthreads();
    for (int off = 128; off > 0; off >>= 1) {
        if (tid < off) { s0[tid] += s0[tid + off]; s1[tid] += s1[tid + off]; }
        __syncthreads();
    }
    if (tid == 0) {
        float l0 = s0[0] + fcb[0], l1 = s1[0] + fcb[1];
        float m = fmaxf(l0, l1);
        float e0 = expf(l0 - m), e1 = expf(l1 - m);
        float inv = 1.0f / (e0 + e1);
        out[b * 2 + 0] = e0 * inv;
        out[b * 2 + 1] = e1 * inv;
    }
}

// ---------------- launch ----------------
extern "C" void kernel_launch(void* const* d_in, const int* in_sizes, int n_in,
                              void* d_out, int out_size) {
    const int*   sents = (const int*)d_in[0];
    const float* att   = (const float*)d_in[1];
    const float* logits= (const float*)d_in[2];
    const int*   mask  = (const int*)d_in[3];
    const float* wih_f = (const float*)d_in[4];
    const float* whh_f = (const float*)d_in[5];
    const float* bih_f = (const float*)d_in[6];
    const float* bhh_f = (const float*)d_in[7];
    const float* wih_r = (const float*)d_in[8];
    const float* whh_r = (const float*)d_in[9];
    const float* bih_r = (const float*)d_in[10];
    const float* bhh_r = (const float*)d_in[11];
    const float* fc_w  = (const float*)d_in[12];
    const float* fc_b  = (const float*)d_in[13];
    float* out = (float*)d_out;

    cudaFuncSetAttribute(input_gemm_hmma, cudaFuncAttributeMaxDynamicSharedMemorySize, GM_SMEM);
    cudaFuncSetAttribute(fused_step_kernel, cudaFuncAttributeMaxDynamicSharedMemorySize, GM_SMEM);

    prep_kernel<<<(int)((PREP_TOTAL + 255) / 256), 256>>>(wih_f, wih_r, whh_f, whh_r,
                                                          bih_f, bhh_f, bih_r, bhh_r);
    masters_kernel<<<BH * 2, 256>>>(att, sents);
    build_slide<<<BH, 256>>>(logits, mask);

    // input GEMM: gatesX(2304x3072) = slide @ Wperm^T + bias (gate-interleaved cols)
    input_gemm_hmma<<<dim3(2 * G4 / 128, BH * TT / 128), 256, GM_SMEM>>>();

    lstm0_kernel<<<(2 * BH * HH + 255) / 256, 256>>>();
    for (int s = 1; s < TT; s++) {
        fused_step_kernel<<<dim3(G4 / 128, BH / 128, 2), 256, GM_SMEM>>>(s);
    }

    logits_rep_kernel<<<BATCH, 256>>>(logits, mask);
    final_kernel<<<BATCH, 256>>>(fc_w, fc_b, out);
}

// round 10
// speedup vs baseline: 1.4843x; 1.4843x over previous
#include <cuda_runtime.h>
#include <cuda_bf16.h>
#include <math.h>
#include <stdint.h>

// ---------------- problem constants ----------------
#define BATCH  32
#define HEADS  12
#define SEQ    512
#define LHALF  256
#define DMODEL 768
#define HH     384          // hidden per direction
#define G4     1536         // 4*HH gates
#define DIN    1536         // 2*DMODEL LSTM input
#define BH     384          // BATCH*HEADS
#define TT     6            // SLIDER
#define EPSV   1e-9f

// ---------------- device scratch (no allocs allowed) ----------------
__device__ int   g_master[BH * 2];
__device__ float g_gatesX[(size_t)BH * TT * 2 * G4];   // 2304 x 3072, gate-interleaved cols (4*j+gate), bias folded
__device__ float g_gtmp[(size_t)2 * BH * G4];          // per-step h @ whh^T (gate-interleaved cols)
__device__ float g_c[(size_t)2 * BH * HH];
__device__ float g_compose[(size_t)BH * TT * DMODEL];
__device__ float g_lrep[(size_t)BATCH * DMODEL];

// bf16 split operands (weights gate-interleaved: row' = 4*j + gate)
__device__ __nv_bfloat16 g_slide_h[(size_t)BH * TT * DIN];
__device__ __nv_bfloat16 g_slide_l[(size_t)BH * TT * DIN];
__device__ __nv_bfloat16 g_wih_h[(size_t)2 * G4 * DIN];
__device__ __nv_bfloat16 g_wih_l[(size_t)2 * G4 * DIN];
__device__ __nv_bfloat16 g_whh_h[(size_t)2 * G4 * HH];
__device__ __nv_bfloat16 g_whh_l[(size_t)2 * G4 * HH];
__device__ __nv_bfloat16 g_hb_h[(size_t)2 * BH * HH];     // [dir][n][j]
__device__ __nv_bfloat16 g_hb_l[(size_t)2 * BH * HH];
__device__ float g_bias[2 * G4];                          // gate-interleaved

// ---------------- PTX helpers (baseline PTX only) ----------------
__device__ __forceinline__ uint32_t smem_u32(const void* p) {
    uint32_t a;
    asm("{ .reg .u64 t; cvta.to.shared.u64 t, %1; cvt.u32.u64 %0, t; }" : "=r"(a) : "l"(p));
    return a;
}

#define CP_ASYNC16(sm, gm) \
    asm volatile("cp.async.cg.shared.global [%0], [%1], 16;" :: "r"(sm), "l"(gm) : "memory")
#define CP_COMMIT() asm volatile("cp.async.commit_group;" ::: "memory")
#define CP_WAIT0()  asm volatile("cp.async.wait_group 0;" ::: "memory")

#define LDSM_X4(r0, r1, r2, r3, addr) \
    asm volatile("ldmatrix.sync.aligned.m8n8.x4.shared.b16 {%0,%1,%2,%3}, [%4];" \
        : "=r"(r0), "=r"(r1), "=r"(r2), "=r"(r3) : "r"(addr))

#define MMA_BF16(c0, c1, c2, c3, a0, a1, a2, a3, b0, b1) \
    asm volatile("mma.sync.aligned.m16n8k16.row.col.f32.bf16.bf16.f32 " \
        "{%0,%1,%2,%3}, {%4,%5,%6,%7}, {%8,%9}, {%0,%1,%2,%3};" \
        : "+f"(c0), "+f"(c1), "+f"(c2), "+f"(c3) \
        : "r"(a0), "r"(a1), "r"(a2), "r"(a3), "r"(b0), "r"(b1))

// ---------------- helpers ----------------
__device__ __forceinline__ float sigf(float x) { return 1.0f / (1.0f + expf(-x)); }

__device__ __forceinline__ int window_start(int pos) {
    pos = min(max(pos, 1), LHALF - 2);
    int l = TT / 2;
    if (pos - TT / 2 <= 0) l = pos - 1;
    int r = TT - l;
    if (pos + r >= LHALF - 1) l = TT - (LHALF - pos - 2);
    return pos - l;
}

// ---------------- K1: masters ----------------
__global__ void masters_kernel(const float* __restrict__ att, const int* __restrict__ sents) {
    int bid  = blockIdx.x;
    int half = bid & 1;
    int bh   = bid >> 1;
    int b    = bh / HEADS;

    __shared__ unsigned char seps[LHALF];
    __shared__ float rowsum[LHALF];

    int tid = threadIdx.x;
    {
        int j = half * LHALF + tid;
        seps[tid] = (sents[b * SEQ + j] == 102) ? 1 : 0;
    }
    __syncthreads();

    const float* base = att + ((size_t)bh * SEQ + (size_t)half * LHALF) * SEQ + (size_t)half * LHALF;

    int warp = tid >> 5, lane = tid & 31;
    for (int row = warp; row < LHALF; row += 8) {
        const float4* rp4 = (const float4*)(base + (size_t)row * SEQ);
        float s = 0.0f;
        #pragma unroll
        for (int k = 0; k < 2; k++) {
            int j4 = lane + 32 * k;
            float4 v = __ldg(rp4 + j4);
            int j = j4 * 4;
            s += seps[j]     ? EPSV : v.x;
            s += seps[j + 1] ? EPSV : v.y;
            s += seps[j + 2] ? EPSV : v.z;
            s += seps[j + 3] ? EPSV : v.w;
        }
        #pragma unroll
        for (int off = 16; off > 0; off >>= 1)
            s += __shfl_down_sync(0xffffffffu, s, off);
        if (lane == 0) rowsum[row] = s;
    }
    __syncthreads();

    __shared__ float bv[LHALF];
    __shared__ int   bix[LHALF];
    bv[tid]  = rowsum[tid];
    bix[tid] = tid;
    __syncthreads();
    for (int off = 128; off > 0; off >>= 1) {
        if (tid < off) {
            float vo = bv[tid + off];
            int   io = bix[tid + off];
            if (vo > bv[tid] || (vo == bv[tid] && io < bix[tid])) { bv[tid] = vo; bix[tid] = io; }
        }
        __syncthreads();
    }
    if (tid == 0) g_master[bh * 2 + half] = bix[0];
}

// ---------------- K2: gather windows -> slide (bf16 hi/lo) ----------------
__global__ void build_slide(const float* __restrict__ logits, const int* __restrict__ mask) {
    int bh = blockIdx.x;
    int b  = bh / HEADS;
    __shared__ int sa, sb;
    if (threadIdx.x == 0) {
        sa = window_start(g_master[bh * 2 + 0]);
        sb = window_start(g_master[bh * 2 + 1]);
    }
    __syncthreads();

    for (int idx = threadIdx.x; idx < TT * DIN; idx += blockDim.x) {
        int t = idx / DIN, f = idx % DIN;
        float v;
        if (f < DMODEL) {
            int row = sa + t;
            v = (mask[b * SEQ + row] == 0) ? EPSV
                : logits[((size_t)b * SEQ + row) * DMODEL + f];
        } else {
            int row = LHALF + sb + t;
            v = (mask[b * SEQ + row] == 0) ? EPSV
                : logits[((size_t)b * SEQ + row) * DMODEL + (f - DMODEL)];
        }
        size_t off = (size_t)bh * (TT * DIN) + idx;
        __nv_bfloat16 hi = __float2bfloat16(v);
        g_slide_h[off] = hi;
        g_slide_l[off] = __float2bfloat16(v - __bfloat162float(hi));
    }
}

// ---------------- K3: fused prep (weight splits with gate interleave + bias) ----------------
// Output row within each direction block: row' = 4*j + gate, where src row = gate*HH + j.
#define NW ((size_t)G4 * DIN)    // 2359296
#define NH ((size_t)G4 * HH)     // 589824
#define PREP_TOTAL (2 * NW + 2 * NH + 2 * G4)

__global__ void prep_kernel(const float* __restrict__ wih_f, const float* __restrict__ wih_r,
                            const float* __restrict__ whh_f, const float* __restrict__ whh_r,
                            const float* __restrict__ bihf, const float* __restrict__ bhhf,
                            const float* __restrict__ bihr, const float* __restrict__ bhhr) {
    size_t i = (size_t)blockIdx.x * blockDim.x + threadIdx.x;
    if (i >= PREP_TOTAL) return;
    if (i < 2 * NW + 2 * NH) {
        const float* src;
        __nv_bfloat16 *dh, *dl;
        size_t off;
        int kdim;
        if (i < NW)               { src = wih_f; dh = g_wih_h;      dl = g_wih_l;      off = i;                kdim = DIN; }
        else if (i < 2 * NW)      { src = wih_r; dh = g_wih_h + NW; dl = g_wih_l + NW; off = i - NW;           kdim = DIN; }
        else if (i < 2 * NW + NH) { src = whh_f; dh = g_whh_h;      dl = g_whh_l;      off = i - 2 * NW;       kdim = HH;  }
        else                      { src = whh_r; dh = g_whh_h + NH; dl = g_whh_l + NH; off = i - 2 * NW - NH;  kdim = HH;  }
        size_t row = off / kdim, k = off % kdim;
        int gate = (int)(row / HH), j = (int)(row % HH);
        size_t drow = (size_t)(4 * j + gate);
        float x = src[off];
        __nv_bfloat16 hi = __float2bfloat16(x);
        dh[drow * kdim + k] = hi;
        dl[drow * kdim + k] = __float2bfloat16(x - __bfloat162float(hi));
    } else {
        size_t q = i - (2 * NW + 2 * NH);      // [0, 2*G4)
        int dir = (int)(q / G4);
        int r   = (int)(q % G4);
        int gate = r / HH, j = r % HH;
        float v = dir ? (bihr[r] + bhhr[r]) : (bihf[r] + bhhf[r]);
        g_bias[dir * G4 + 4 * j + gate] = v;
    }
}

// ---------------- GEMM core (round-8: 2-stage cp.async, LDSM hoisted, 3-product) ----------------
#define BK          64
#define CHUNK_BYTES 16384          // 128 rows x 128B (64 bf16)
#define BUF_BYTES   (4 * CHUNK_BYTES)
#define GM_SMEM     (1024 + 2 * BUF_BYTES)

__device__ __forceinline__ void gemm_core(
    const __nv_bfloat16* Ah, const __nv_bfloat16* Al,
    const __nv_bfloat16* Bh, const __nv_bfloat16* Bl,
    int bm, int bn, int K, int NC,
    char* smem_raw, uint32_t tiles_u,
    int tid, int lane, int wm, int wn,
    float acc[4][4][4])
{
    int Kd8 = K >> 3;
    const __nv_bfloat16* srcs[4] = {Ah, Al, Bh, Bl};
    int rows0[4] = {bm, bm, bn, bn};

    auto load_chunk = [&](int c, int buf) {
        int k0 = c * BK;
        uint32_t bufu = tiles_u + buf * BUF_BYTES;
        #pragma unroll
        for (int t4 = 0; t4 < 4; t4++) {
            const uint4* gp = (const uint4*)(srcs[t4] + (size_t)rows0[t4] * K + k0);
            uint32_t tb = bufu + t4 * CHUNK_BYTES;
            #pragma unroll
            for (int i = 0; i < 4; i++) {
                int u = tid + i * 256;
                int r = u >> 3, c16 = u & 7;
                const uint4* ga = gp + (size_t)r * Kd8 + c16;
                uint32_t off = (uint32_t)(r * 128 + c16 * 16);
                uint32_t sw = off ^ ((off >> 3) & 0x70);
                CP_ASYNC16(tb + sw, ga);
            }
        }
    };

    load_chunk(0, 0);
    CP_COMMIT();

    for (int c = 0; c < NC; c++) {
        CP_WAIT0();
        __syncthreads();
        if (c + 1 < NC) { load_chunk(c + 1, (c + 1) & 1); CP_COMMIT(); }

        uint32_t base = tiles_u + (c & 1) * BUF_BYTES;
        uint32_t ah_base = base;
        uint32_t al_base = base + CHUNK_BYTES;
        uint32_t bh_base = base + 2 * CHUNK_BYTES;
        uint32_t bl_base = base + 3 * CHUNK_BYTES;

        #pragma unroll
        for (int ks = 0; ks < 4; ks++) {
            uint32_t a_h[4][4], a_l[4][4];
            #pragma unroll
            for (int mt = 0; mt < 4; mt++) {
                uint32_t r = wm + mt * 16 + (lane & 15);
                uint32_t coloff = ks * 32 + ((lane >> 4) & 1) * 16;
                uint32_t off = r * 128 + coloff;
                uint32_t sw = off ^ ((off >> 3) & 0x70);
                LDSM_X4(a_h[mt][0], a_h[mt][1], a_h[mt][2], a_h[mt][3], ah_base + sw);
                LDSM_X4(a_l[mt][0], a_l[mt][1], a_l[mt][2], a_l[mt][3], al_base + sw);
            }
            uint32_t b_h[4][2], b_l[4][2];
            #pragma unroll
            for (int h = 0; h < 2; h++) {
                uint32_t r = wn + h * 16 + (lane & 7) + ((lane >> 4) << 3);
                uint32_t coloff = ks * 32 + ((lane >> 3) & 1) * 16;
                uint32_t off = r * 128 + coloff;
                uint32_t sw = off ^ ((off >> 3) & 0x70);
                uint32_t r0, r1, r2, r3;
                LDSM_X4(r0, r1, r2, r3, bh_base + sw);
                b_h[2 * h][0] = r0; b_h[2 * h][1] = r1;
                b_h[2 * h + 1][0] = r2; b_h[2 * h + 1][1] = r3;
                LDSM_X4(r0, r1, r2, r3, bl_base + sw);
                b_l[2 * h][0] = r0; b_l[2 * h][1] = r1;
                b_l[2 * h + 1][0] = r2; b_l[2 * h + 1][1] = r3;
            }
            #pragma unroll
            for (int mt = 0; mt < 4; mt++)
                #pragma unroll
                for (int nt = 0; nt < 4; nt++)
                    MMA_BF16(acc[mt][nt][0], acc[mt][nt][1], acc[mt][nt][2], acc[mt][nt][3],
                             a_h[mt][0], a_h[mt][1], a_h[mt][2], a_h[mt][3],
                             b_h[nt][0], b_h[nt][1]);
            #pragma unroll
            for (int mt = 0; mt < 4; mt++)
                #pragma unroll
                for (int nt = 0; nt < 4; nt++)
                    MMA_BF16(acc[mt][nt][0], acc[mt][nt][1], acc[mt][nt][2], acc[mt][nt][3],
                             a_h[mt][0], a_h[mt][1], a_h[mt][2], a_h[mt][3],
                             b_l[nt][0], b_l[nt][1]);
            #pragma unroll
            for (int mt = 0; mt < 4; mt++)
                #pragma unroll
                for (int nt = 0; nt < 4; nt++)
                    MMA_BF16(acc[mt][nt][0], acc[mt][nt][1], acc[mt][nt][2], acc[mt][nt][3],
                             a_l[mt][0], a_l[mt][1], a_l[mt][2], a_l[mt][3],
                             b_h[nt][0], b_h[nt][1]);
        }
        __syncthreads();
    }
}

// ---------------- K4: input GEMM ----------------
__global__ __launch_bounds__(256, 1) void input_gemm_hmma() {
    extern __shared__ char smem_raw[];
    uint32_t smem_u = smem_u32(smem_raw);
    uint32_t tiles_u = (smem_u + 1023) & ~1023u;

    int tid = threadIdx.x, wid = tid >> 5, lane = tid & 31;
    int wm = (wid & 1) * 64, wn = (wid >> 1) * 32;
    int bm = blockIdx.y * 128;
    int bn = blockIdx.x * 128;

    float acc[4][4][4];
    #pragma unroll
    for (int i = 0; i < 4; i++)
        #pragma unroll
        for (int j = 0; j < 4; j++)
            #pragma unroll
            for (int q = 0; q < 4; q++) acc[i][j][q] = 0.0f;

    gemm_core(g_slide_h, g_slide_l, g_wih_h, g_wih_l,
              bm, bn, DIN, DIN / BK, smem_raw, tiles_u, tid, lane, wm, wn, acc);

    #pragma unroll
    for (int mt = 0; mt < 4; mt++) {
        #pragma unroll
        for (int nt = 0; nt < 4; nt++) {
            int row = bm + wm + mt * 16 + (lane >> 2);
            int col = bn + wn + nt * 8 + (lane & 3) * 2;
            float b0 = g_bias[col], b1 = g_bias[col + 1];
            float2 v0 = make_float2(acc[mt][nt][0] + b0, acc[mt][nt][1] + b1);
            float2 v1 = make_float2(acc[mt][nt][2] + b0, acc[mt][nt][3] + b1);
            *(float2*)(g_gatesX + (size_t)row * (2 * G4) + col) = v0;
            *(float2*)(g_gatesX + (size_t)(row + 8) * (2 * G4) + col) = v1;
        }
    }
}

// ---------------- K5: recurrent GEMM  gtmp[dir] = h[dir] @ whh[dir]^T ----------------
__global__ __launch_bounds__(256, 1) void rec_gemm_hmma() {
    extern __shared__ char smem_raw[];
    uint32_t smem_u = smem_u32(smem_raw);
    uint32_t tiles_u = (smem_u + 1023) & ~1023u;

    int z = blockIdx.z;
    const __nv_bfloat16* Ah = g_hb_h + (size_t)z * BH * HH;
    const __nv_bfloat16* Al = g_hb_l + (size_t)z * BH * HH;
    const __nv_bfloat16* Bh = g_whh_h + (size_t)z * G4 * HH;
    const __nv_bfloat16* Bl = g_whh_l + (size_t)z * G4 * HH;
    float* C = g_gtmp + (size_t)z * BH * G4;

    int tid = threadIdx.x, wid = tid >> 5, lane = tid & 31;
    int wm = (wid & 1) * 64, wn = (wid >> 1) * 32;
    int bm = blockIdx.y * 128;
    int bn = blockIdx.x * 128;

    float acc[4][4][4];
    #pragma unroll
    for (int i = 0; i < 4; i++)
        #pragma unroll
        for (int j = 0; j < 4; j++)
            #pragma unroll
            for (int q = 0; q < 4; q++) acc[i][j][q] = 0.0f;

    gemm_core(Ah, Al, Bh, Bl, bm, bn, HH, HH / BK,
              smem_raw, tiles_u, tid, lane, wm, wn, acc);

    #pragma unroll
    for (int mt = 0; mt < 4; mt++) {
        #pragma unroll
        for (int nt = 0; nt < 4; nt++) {
            int row = bm + wm + mt * 16 + (lane >> 2);
            int col = bn + wn + nt * 8 + (lane & 3) * 2;
            float2 v0 = make_float2(acc[mt][nt][0], acc[mt][nt][1]);
            float2 v1 = make_float2(acc[mt][nt][2], acc[mt][nt][3]);
            *(float2*)(C + (size_t)row * G4 + col) = v0;
            *(float2*)(C + (size_t)(row + 8) * G4 + col) = v1;
        }
    }
}

// ---------------- K6: per-step LSTM pointwise (gate-interleaved float4 reads) ----------------
__global__ void lstm_point(int s) {
    int idx = blockIdx.x * blockDim.x + threadIdx.x;
    if (idx >= 2 * BH * HH) return;
    int dir = idx / (BH * HH);
    int r   = idx % (BH * HH);
    int n   = r / HH;
    int j   = r % HH;
    int t   = dir ? (TT - 1 - s) : s;

    float4 gx = *(const float4*)(g_gatesX + ((size_t)(n * TT + t)) * (2 * G4)
                                 + (size_t)dir * G4 + 4 * j);
    float gi = gx.x, gf = gx.y, gg = gx.z, go = gx.w;

    float c;
    if (s == 0) {
        c = sigf(gi) * tanhf(gg);
    } else {
        float4 gt = *(const float4*)(g_gtmp + (size_t)dir * BH * G4 + (size_t)n * G4 + 4 * j);
        gi += gt.x; gf += gt.y; gg += gt.z; go += gt.w;
        c = sigf(gf) * g_c[idx] + sigf(gi) * tanhf(gg);
    }
    float h = sigf(go) * tanhf(c);
    g_c[idx] = c;
    __nv_bfloat16 hi = __float2bfloat16(h);
    g_hb_h[idx] = hi;
    g_hb_l[idx] = __float2bfloat16(h - __bfloat162float(hi));
    g_compose[((size_t)n * TT + t) * DMODEL + dir * HH + j] = h;
}

// ---------------- K7: logits_rep (parallelized over d-chunks) ----------------
__global__ void logits_rep_kernel(const float* __restrict__ logits, const int* __restrict__ mask) {
    int b = blockIdx.x;
    int d = blockIdx.y * 128 + threadIdx.x;   // 6 blocks/batch, 128 threads each
    int tid = threadIdx.x;

    __shared__ unsigned char repl[SEQ];
    for (int i = tid; i < SEQ; i += blockDim.x) repl[i] = 0;
    __syncthreads();
    if (tid < 2 * HEADS) {
        int h = tid >> 1, half = tid & 1;
        int st = window_start(g_master[(b * HEADS + h) * 2 + half]);
        int base = half * LHALF + st;
        for (int k = 0; k < TT; k++) repl[base + k] = 1;
    }
    __syncthreads();
    for (int sPos = tid; sPos < SEQ; sPos += blockDim.x)
        repl[sPos] = (repl[sPos] && mask[b * SEQ + sPos] == 0) ? 1 : 0;
    __syncthreads();

    float a0 = 0.f, a1 = 0.f, a2 = 0.f, a3 = 0.f;
    const float* lp = logits + (size_t)b * SEQ * DMODEL + d;
    for (int sPos = 0; sPos < SEQ; sPos += 4) {
        float v0 = __ldg(lp + (size_t)(sPos + 0) * DMODEL);
        float v1 = __ldg(lp + (size_t)(sPos + 1) * DMODEL);
        float v2 = __ldg(lp + (size_t)(sPos + 2) * DMODEL);
        float v3 = __ldg(lp + (size_t)(sPos + 3) * DMODEL);
        a0 += repl[sPos]     ? EPSV : v0;
        a1 += repl[sPos + 1] ? EPSV : v1;
        a2 += repl[sPos + 2] ? EPSV : v2;
        a3 += repl[sPos + 3] ? EPSV : v3;
    }
    g_lrep[(size_t)b * DMODEL + d] = (a0 + a1 + a2 + a3) * (1.0f / (float)SEQ);
}

// ---------------- K8: final FC + softmax ----------------
__global__ void final_kernel(const float* __restrict__ fcw, const float* __restrict__ fcb,
                             float* __restrict__ out) {
    int b = blockIdx.x;
    int tid = threadIdx.x;
    const int NF = DMODEL * (HEADS + 1);
    float a0 = 0.0f, a1 = 0.0f;

    for (int j = tid; j < NF; j += 256) {
        float x;
        if (j < HEADS * DMODEL) {
            int h = j / DMODEL, d = j % DMODEL;
            int n = b * HEADS + h;
            const float* cp = g_compose + (size_t)n * TT * DMODEL + d;
            float s = 0.0f;
            #pragma unroll
            for (int t = 0; t < TT; t++) s += cp[(size_t)t * DMODEL];
            x = s * (1.0f / (float)TT);
        } else {
            x = g_lrep[(size_t)b * DMODEL + (j - HEADS * DMODEL)];
        }
        a0 += x * fcw[j];
        a1 += x * fcw[NF + j];
    }

    __shared__ float s0[256], s1[256];
    s0[tid] = a0; s1[tid] = a1;
    __syncthreads();
    for (int off = 128; off > 0; off >>= 1) {
        if (tid < off) { s0[tid] += s0[tid + off]; s1[tid] += s1[tid + off]; }
        __syncthreads();
    }
    if (tid == 0) {
        float l0 = s0[0] + fcb[0], l1 = s1[0] + fcb[1];
        float m = fmaxf(l0, l1);
        float e0 = expf(l0 - m), e1 = expf(l1 - m);
        float inv = 1.0f / (e0 + e1);
        out[b * 2 + 0] = e0 * inv;
        out[b * 2 + 1] = e1 * inv;
    }
}

// ---------------- launch ----------------
extern "C" void kernel_launch(void* const* d_in, const int* in_sizes, int n_in,
                              void* d_out, int out_size) {
    const int*   sents = (const int*)d_in[0];
    const float* att   = (const float*)d_in[1];
    const float* logits= (const float*)d_in[2];
    const int*   mask  = (const int*)d_in[3];
    const float* wih_f = (const float*)d_in[4];
    const float* whh_f = (const float*)d_in[5];
    const float* bih_f = (const float*)d_in[6];
    const float* bhh_f = (const float*)d_in[7];
    const float* wih_r = (const float*)d_in[8];
    const float* whh_r = (const float*)d_in[9];
    const float* bih_r = (const float*)d_in[10];
    const float* bhh_r = (const float*)d_in[11];
    const float* fc_w  = (const float*)d_in[12];
    const float* fc_b  = (const float*)d_in[13];
    float* out = (float*)d_out;

    cudaFuncSetAttribute(input_gemm_hmma, cudaFuncAttributeMaxDynamicSharedMemorySize, GM_SMEM);
    cudaFuncSetAttribute(rec_gemm_hmma, cudaFuncAttributeMaxDynamicSharedMemorySize, GM_SMEM);

    prep_kernel<<<(int)((PREP_TOTAL + 255) / 256), 256>>>(wih_f, wih_r, whh_f, whh_r,
                                                          bih_f, bhh_f, bih_r, bhh_r);
    masters_kernel<<<BH * 2, 256>>>(att, sents);
    build_slide<<<BH, 256>>>(logits, mask);

    // input GEMM: gatesX(2304x3072) = slide @ Wperm^T + bias (gate-interleaved cols)
    input_gemm_hmma<<<dim3(2 * G4 / 128, BH * TT / 128), 256, GM_SMEM>>>();

    for (int s = 0; s < TT; s++) {
        lstm_point<<<(2 * BH * HH + 255) / 256, 256>>>(s);
        if (s < TT - 1) {
            rec_gemm_hmma<<<dim3(G4 / 128, BH / 128, 2), 256, GM_SMEM>>>();
        }
    }

    logits_rep_kernel<<<dim3(BATCH, DMODEL / 128), 128>>>(logits, mask);
    final_kernel<<<BATCH, 256>>>(fc_w, fc_b, out);
}

// round 11
// speedup vs baseline: 1.4892x; 1.0033x over previous
#include <cuda_runtime.h>
#include <cuda_bf16.h>
#include <math.h>
#include <stdint.h>

// ---------------- problem constants ----------------
#define BATCH  32
#define HEADS  12
#define SEQ    512
#define LHALF  256
#define DMODEL 768
#define HH     384          // hidden per direction
#define G4     1536         // 4*HH gates
#define DIN    1536         // 2*DMODEL LSTM input
#define BH     384          // BATCH*HEADS
#define TT     6            // SLIDER
#define EPSV   1e-9f

// ---------------- device scratch (no allocs allowed) ----------------
__device__ int   g_master[BH * 2];
__device__ float g_gatesX[(size_t)BH * TT * 2 * G4];   // 2304 x 3072, gate-interleaved cols (4*j+gate), bias folded
__device__ float g_gtmp[(size_t)2 * BH * G4];          // per-step h @ whh^T (gate-interleaved cols)
__device__ float g_c[(size_t)2 * BH * HH];
__device__ float g_compose[(size_t)BH * TT * DMODEL];
__device__ float g_lrep[(size_t)BATCH * DMODEL];

// bf16 split operands (weights gate-interleaved: row' = 4*j + gate)
__device__ __nv_bfloat16 g_slide_h[(size_t)BH * TT * DIN];
__device__ __nv_bfloat16 g_slide_l[(size_t)BH * TT * DIN];
__device__ __nv_bfloat16 g_wih_h[(size_t)2 * G4 * DIN];
__device__ __nv_bfloat16 g_wih_l[(size_t)2 * G4 * DIN];
__device__ __nv_bfloat16 g_whh_h[(size_t)2 * G4 * HH];
__device__ __nv_bfloat16 g_whh_l[(size_t)2 * G4 * HH];
__device__ __nv_bfloat16 g_hb_h[(size_t)2 * BH * HH];     // [dir][n][j]
__device__ __nv_bfloat16 g_hb_l[(size_t)2 * BH * HH];
__device__ float g_bias[2 * G4];                          // gate-interleaved

// ---------------- PTX helpers (baseline PTX only) ----------------
__device__ __forceinline__ uint32_t smem_u32(const void* p) {
    uint32_t a;
    asm("{ .reg .u64 t; cvta.to.shared.u64 t, %1; cvt.u32.u64 %0, t; }" : "=r"(a) : "l"(p));
    return a;
}

#define CP_ASYNC16(sm, gm) \
    asm volatile("cp.async.cg.shared.global [%0], [%1], 16;" :: "r"(sm), "l"(gm) : "memory")
#define CP_COMMIT() asm volatile("cp.async.commit_group;" ::: "memory")
#define CP_WAIT0()  asm volatile("cp.async.wait_group 0;" ::: "memory")

#define LDSM_X4(r0, r1, r2, r3, addr) \
    asm volatile("ldmatrix.sync.aligned.m8n8.x4.shared.b16 {%0,%1,%2,%3}, [%4];" \
        : "=r"(r0), "=r"(r1), "=r"(r2), "=r"(r3) : "r"(addr))

#define MMA_BF16(c0, c1, c2, c3, a0, a1, a2, a3, b0, b1) \
    asm volatile("mma.sync.aligned.m16n8k16.row.col.f32.bf16.bf16.f32 " \
        "{%0,%1,%2,%3}, {%4,%5,%6,%7}, {%8,%9}, {%0,%1,%2,%3};" \
        : "+f"(c0), "+f"(c1), "+f"(c2), "+f"(c3) \
        : "r"(a0), "r"(a1), "r"(a2), "r"(a3), "r"(b0), "r"(b1))

// ---------------- helpers ----------------
__device__ __forceinline__ float sigf(float x) { return 1.0f / (1.0f + expf(-x)); }

__device__ __forceinline__ int window_start(int pos) {
    pos = min(max(pos, 1), LHALF - 2);
    int l = TT / 2;
    if (pos - TT / 2 <= 0) l = pos - 1;
    int r = TT - l;
    if (pos + r >= LHALF - 1) l = TT - (LHALF - pos - 2);
    return pos - l;
}

// ---------------- K1: masters (deep-MLP row sums) ----------------
__global__ void masters_kernel(const float* __restrict__ att, const int* __restrict__ sents) {
    int bid  = blockIdx.x;
    int half = bid & 1;
    int bh   = bid >> 1;
    int b    = bh / HEADS;

    __shared__ unsigned char seps[LHALF];
    __shared__ float rowsum[LHALF];

    int tid = threadIdx.x;
    {
        int j = half * LHALF + tid;
        seps[tid] = (sents[b * SEQ + j] == 102) ? 1 : 0;
    }
    __syncthreads();

    const float* base = att + ((size_t)bh * SEQ + (size_t)half * LHALF) * SEQ + (size_t)half * LHALF;

    int warp = tid >> 5, lane = tid & 31;
    // each warp owns 32 consecutive rows; process 4 rows/iter -> 8 loads in flight
    #pragma unroll
    for (int rr = 0; rr < 32; rr += 4) {
        int row = warp * 32 + rr;
        const float4* r0 = (const float4*)(base + (size_t)(row + 0) * SEQ);
        const float4* r1 = (const float4*)(base + (size_t)(row + 1) * SEQ);
        const float4* r2 = (const float4*)(base + (size_t)(row + 2) * SEQ);
        const float4* r3 = (const float4*)(base + (size_t)(row + 3) * SEQ);
        float4 v0a = __ldg(r0 + lane), v0b = __ldg(r0 + lane + 32);
        float4 v1a = __ldg(r1 + lane), v1b = __ldg(r1 + lane + 32);
        float4 v2a = __ldg(r2 + lane), v2b = __ldg(r2 + lane + 32);
        float4 v3a = __ldg(r3 + lane), v3b = __ldg(r3 + lane + 32);

        int ja = lane * 4, jb = (lane + 32) * 4;
        float m0a = seps[ja] ? EPSV : v0a.x, m1a = seps[ja+1] ? EPSV : v0a.y,
              m2a = seps[ja+2] ? EPSV : v0a.z, m3a = seps[ja+3] ? EPSV : v0a.w;
        float s0 = m0a + m1a + m2a + m3a;
        s0 += (seps[jb] ? EPSV : v0b.x) + (seps[jb+1] ? EPSV : v0b.y)
            + (seps[jb+2] ? EPSV : v0b.z) + (seps[jb+3] ? EPSV : v0b.w);
        float s1 = (seps[ja] ? EPSV : v1a.x) + (seps[ja+1] ? EPSV : v1a.y)
                 + (seps[ja+2] ? EPSV : v1a.z) + (seps[ja+3] ? EPSV : v1a.w)
                 + (seps[jb] ? EPSV : v1b.x) + (seps[jb+1] ? EPSV : v1b.y)
                 + (seps[jb+2] ? EPSV : v1b.z) + (seps[jb+3] ? EPSV : v1b.w);
        float s2 = (seps[ja] ? EPSV : v2a.x) + (seps[ja+1] ? EPSV : v2a.y)
                 + (seps[ja+2] ? EPSV : v2a.z) + (seps[ja+3] ? EPSV : v2a.w)
                 + (seps[jb] ? EPSV : v2b.x) + (seps[jb+1] ? EPSV : v2b.y)
                 + (seps[jb+2] ? EPSV : v2b.z) + (seps[jb+3] ? EPSV : v2b.w);
        float s3 = (seps[ja] ? EPSV : v3a.x) + (seps[ja+1] ? EPSV : v3a.y)
                 + (seps[ja+2] ? EPSV : v3a.z) + (seps[ja+3] ? EPSV : v3a.w)
                 + (seps[jb] ? EPSV : v3b.x) + (seps[jb+1] ? EPSV : v3b.y)
                 + (seps[jb+2] ? EPSV : v3b.z) + (seps[jb+3] ? EPSV : v3b.w);

        #pragma unroll
        for (int off = 16; off > 0; off >>= 1) {
            s0 += __shfl_down_sync(0xffffffffu, s0, off);
            s1 += __shfl_down_sync(0xffffffffu, s1, off);
            s2 += __shfl_down_sync(0xffffffffu, s2, off);
            s3 += __shfl_down_sync(0xffffffffu, s3, off);
        }
        if (lane == 0) {
            rowsum[row]     = s0;
            rowsum[row + 1] = s1;
            rowsum[row + 2] = s2;
            rowsum[row + 3] = s3;
        }
    }
    __syncthreads();

    __shared__ float bv[LHALF];
    __shared__ int   bix[LHALF];
    bv[tid]  = rowsum[tid];
    bix[tid] = tid;
    __syncthreads();
    for (int off = 128; off > 0; off >>= 1) {
        if (tid < off) {
            float vo = bv[tid + off];
            int   io = bix[tid + off];
            if (vo > bv[tid] || (vo == bv[tid] && io < bix[tid])) { bv[tid] = vo; bix[tid] = io; }
        }
        __syncthreads();
    }
    if (tid == 0) g_master[bh * 2 + half] = bix[0];
}

// ---------------- K2: gather windows -> slide (bf16 hi/lo) ----------------
__global__ void build_slide(const float* __restrict__ logits, const int* __restrict__ mask) {
    int bh = blockIdx.x;
    int b  = bh / HEADS;
    __shared__ int sa, sb;
    if (threadIdx.x == 0) {
        sa = window_start(g_master[bh * 2 + 0]);
        sb = window_start(g_master[bh * 2 + 1]);
    }
    __syncthreads();

    for (int idx = threadIdx.x; idx < TT * DIN; idx += blockDim.x) {
        int t = idx / DIN, f = idx % DIN;
        float v;
        if (f < DMODEL) {
            int row = sa + t;
            v = (mask[b * SEQ + row] == 0) ? EPSV
                : logits[((size_t)b * SEQ + row) * DMODEL + f];
        } else {
            int row = LHALF + sb + t;
            v = (mask[b * SEQ + row] == 0) ? EPSV
                : logits[((size_t)b * SEQ + row) * DMODEL + (f - DMODEL)];
        }
        size_t off = (size_t)bh * (TT * DIN) + idx;
        __nv_bfloat16 hi = __float2bfloat16(v);
        g_slide_h[off] = hi;
        g_slide_l[off] = __float2bfloat16(v - __bfloat162float(hi));
    }
}

// ---------------- K3: fused prep (weight splits with gate interleave + bias) ----------------
// Output row within each direction block: row' = 4*j + gate, where src row = gate*HH + j.
#define NW ((size_t)G4 * DIN)    // 2359296
#define NH ((size_t)G4 * HH)     // 589824
#define PREP_TOTAL (2 * NW + 2 * NH + 2 * G4)

__global__ void prep_kernel(const float* __restrict__ wih_f, const float* __restrict__ wih_r,
                            const float* __restrict__ whh_f, const float* __restrict__ whh_r,
                            const float* __restrict__ bihf, const float* __restrict__ bhhf,
                            const float* __restrict__ bihr, const float* __restrict__ bhhr) {
    size_t i = (size_t)blockIdx.x * blockDim.x + threadIdx.x;
    if (i >= PREP_TOTAL) return;
    if (i < 2 * NW + 2 * NH) {
        const float* src;
        __nv_bfloat16 *dh, *dl;
        size_t off;
        int kdim;
        if (i < NW)               { src = wih_f; dh = g_wih_h;      dl = g_wih_l;      off = i;                kdim = DIN; }
        else if (i < 2 * NW)      { src = wih_r; dh = g_wih_h + NW; dl = g_wih_l + NW; off = i - NW;           kdim = DIN; }
        else if (i < 2 * NW + NH) { src = whh_f; dh = g_whh_h;      dl = g_whh_l;      off = i - 2 * NW;       kdim = HH;  }
        else                      { src = whh_r; dh = g_whh_h + NH; dl = g_whh_l + NH; off = i - 2 * NW - NH;  kdim = HH;  }
        size_t row = off / kdim, k = off % kdim;
        int gate = (int)(row / HH), j = (int)(row % HH);
        size_t drow = (size_t)(4 * j + gate);
        float x = src[off];
        __nv_bfloat16 hi = __float2bfloat16(x);
        dh[drow * kdim + k] = hi;
        dl[drow * kdim + k] = __float2bfloat16(x - __bfloat162float(hi));
    } else {
        size_t q = i - (2 * NW + 2 * NH);      // [0, 2*G4)
        int dir = (int)(q / G4);
        int r   = (int)(q % G4);
        int gate = r / HH, j = r % HH;
        float v = dir ? (bihr[r] + bhhr[r]) : (bihf[r] + bhhf[r]);
        g_bias[dir * G4 + 4 * j + gate] = v;
    }
}

// ---------------- GEMM core (2-stage cp.async, LDSM hoisted, 3-product, reordered) ----------------
#define BK          64
#define CHUNK_BYTES 16384          // 128 rows x 128B (64 bf16)
#define BUF_BYTES   (4 * CHUNK_BYTES)
#define GM_SMEM     (1024 + 2 * BUF_BYTES)

__device__ __forceinline__ void gemm_core(
    const __nv_bfloat16* Ah, const __nv_bfloat16* Al,
    const __nv_bfloat16* Bh, const __nv_bfloat16* Bl,
    int bm, int bn, int K, int NC,
    char* smem_raw, uint32_t tiles_u,
    int tid, int lane, int wm, int wn,
    float acc[4][4][4])
{
    int Kd8 = K >> 3;
    const __nv_bfloat16* srcs[4] = {Ah, Al, Bh, Bl};
    int rows0[4] = {bm, bm, bn, bn};

    auto load_chunk = [&](int c, int buf) {
        int k0 = c * BK;
        uint32_t bufu = tiles_u + buf * BUF_BYTES;
        #pragma unroll
        for (int t4 = 0; t4 < 4; t4++) {
            const uint4* gp = (const uint4*)(srcs[t4] + (size_t)rows0[t4] * K + k0);
            uint32_t tb = bufu + t4 * CHUNK_BYTES;
            #pragma unroll
            for (int i = 0; i < 4; i++) {
                int u = tid + i * 256;
                int r = u >> 3, c16 = u & 7;
                const uint4* ga = gp + (size_t)r * Kd8 + c16;
                uint32_t off = (uint32_t)(r * 128 + c16 * 16);
                uint32_t sw = off ^ ((off >> 3) & 0x70);
                CP_ASYNC16(tb + sw, ga);
            }
        }
    };

    load_chunk(0, 0);
    CP_COMMIT();

    for (int c = 0; c < NC; c++) {
        CP_WAIT0();
        __syncthreads();
        if (c + 1 < NC) { load_chunk(c + 1, (c + 1) & 1); CP_COMMIT(); }

        uint32_t base = tiles_u + (c & 1) * BUF_BYTES;
        uint32_t ah_base = base;
        uint32_t al_base = base + CHUNK_BYTES;
        uint32_t bh_base = base + 2 * CHUNK_BYTES;
        uint32_t bl_base = base + 3 * CHUNK_BYTES;

        #pragma unroll
        for (int ks = 0; ks < 4; ks++) {
            // ---- hi fragments first ----
            uint32_t a_h[4][4];
            #pragma unroll
            for (int mt = 0; mt < 4; mt++) {
                uint32_t r = wm + mt * 16 + (lane & 15);
                uint32_t coloff = ks * 32 + ((lane >> 4) & 1) * 16;
                uint32_t off = r * 128 + coloff;
                uint32_t sw = off ^ ((off >> 3) & 0x70);
                LDSM_X4(a_h[mt][0], a_h[mt][1], a_h[mt][2], a_h[mt][3], ah_base + sw);
            }
            uint32_t b_h[4][2];
            #pragma unroll
            for (int h = 0; h < 2; h++) {
                uint32_t r = wn + h * 16 + (lane & 7) + ((lane >> 4) << 3);
                uint32_t coloff = ks * 32 + ((lane >> 3) & 1) * 16;
                uint32_t off = r * 128 + coloff;
                uint32_t sw = off ^ ((off >> 3) & 0x70);
                uint32_t r0, r1, r2, r3;
                LDSM_X4(r0, r1, r2, r3, bh_base + sw);
                b_h[2 * h][0] = r0; b_h[2 * h][1] = r1;
                b_h[2 * h + 1][0] = r2; b_h[2 * h + 1][1] = r3;
            }
            // pass 1: Ah x Bh (starts while lo fragments load below)
            #pragma unroll
            for (int mt = 0; mt < 4; mt++)
                #pragma unroll
                for (int nt = 0; nt < 4; nt++)
                    MMA_BF16(acc[mt][nt][0], acc[mt][nt][1], acc[mt][nt][2], acc[mt][nt][3],
                             a_h[mt][0], a_h[mt][1], a_h[mt][2], a_h[mt][3],
                             b_h[nt][0], b_h[nt][1]);
            // ---- lo fragments ----
            uint32_t a_l[4][4];
            #pragma unroll
            for (int mt = 0; mt < 4; mt++) {
                uint32_t r = wm + mt * 16 + (lane & 15);
                uint32_t coloff = ks * 32 + ((lane >> 4) & 1) * 16;
                uint32_t off = r * 128 + coloff;
                uint32_t sw = off ^ ((off >> 3) & 0x70);
                LDSM_X4(a_l[mt][0], a_l[mt][1], a_l[mt][2], a_l[mt][3], al_base + sw);
            }
            uint32_t b_l[4][2];
            #pragma unroll
            for (int h = 0; h < 2; h++) {
                uint32_t r = wn + h * 16 + (lane & 7) + ((lane >> 4) << 3);
                uint32_t coloff = ks * 32 + ((lane >> 3) & 1) * 16;
                uint32_t off = r * 128 + coloff;
                uint32_t sw = off ^ ((off >> 3) & 0x70);
                uint32_t r0, r1, r2, r3;
                LDSM_X4(r0, r1, r2, r3, bl_base + sw);
                b_l[2 * h][0] = r0; b_l[2 * h][1] = r1;
                b_l[2 * h + 1][0] = r2; b_l[2 * h + 1][1] = r3;
            }
            // pass 2: Ah x Bl
            #pragma unroll
            for (int mt = 0; mt < 4; mt++)
                #pragma unroll
                for (int nt = 0; nt < 4; nt++)
                    MMA_BF16(acc[mt][nt][0], acc[mt][nt][1], acc[mt][nt][2], acc[mt][nt][3],
                             a_h[mt][0], a_h[mt][1], a_h[mt][2], a_h[mt][3],
                             b_l[nt][0], b_l[nt][1]);
            // pass 3: Al x Bh
            #pragma unroll
            for (int mt = 0; mt < 4; mt++)
                #pragma unroll
                for (int nt = 0; nt < 4; nt++)
                    MMA_BF16(acc[mt][nt][0], acc[mt][nt][1], acc[mt][nt][2], acc[mt][nt][3],
                             a_l[mt][0], a_l[mt][1], a_l[mt][2], a_l[mt][3],
                             b_h[nt][0], b_h[nt][1]);
        }
        __syncthreads();
    }
}

// ---------------- K4: input GEMM ----------------
__global__ __launch_bounds__(256, 1) void input_gemm_hmma() {
    extern __shared__ char smem_raw[];
    uint32_t smem_u = smem_u32(smem_raw);
    uint32_t tiles_u = (smem_u + 1023) & ~1023u;

    int tid = threadIdx.x, wid = tid >> 5, lane = tid & 31;
    int wm = (wid & 1) * 64, wn = (wid >> 1) * 32;
    int bm = blockIdx.y * 128;
    int bn = blockIdx.x * 128;

    float acc[4][4][4];
    #pragma unroll
    for (int i = 0; i < 4; i++)
        #pragma unroll
        for (int j = 0; j < 4; j++)
            #pragma unroll
            for (int q = 0; q < 4; q++) acc[i][j][q] = 0.0f;

    gemm_core(g_slide_h, g_slide_l, g_wih_h, g_wih_l,
              bm, bn, DIN, DIN / BK, smem_raw, tiles_u, tid, lane, wm, wn, acc);

    #pragma unroll
    for (int mt = 0; mt < 4; mt++) {
        #pragma unroll
        for (int nt = 0; nt < 4; nt++) {
            int row = bm + wm + mt * 16 + (lane >> 2);
            int col = bn + wn + nt * 8 + (lane & 3) * 2;
            float b0 = g_bias[col], b1 = g_bias[col + 1];
            float2 v0 = make_float2(acc[mt][nt][0] + b0, acc[mt][nt][1] + b1);
            float2 v1 = make_float2(acc[mt][nt][2] + b0, acc[mt][nt][3] + b1);
            *(float2*)(g_gatesX + (size_t)row * (2 * G4) + col) = v0;
            *(float2*)(g_gatesX + (size_t)(row + 8) * (2 * G4) + col) = v1;
        }
    }
}

// ---------------- K5: recurrent GEMM  gtmp[dir] = h[dir] @ whh[dir]^T ----------------
__global__ __launch_bounds__(256, 1) void rec_gemm_hmma() {
    extern __shared__ char smem_raw[];
    uint32_t smem_u = smem_u32(smem_raw);
    uint32_t tiles_u = (smem_u + 1023) & ~1023u;

    int z = blockIdx.z;
    const __nv_bfloat16* Ah = g_hb_h + (size_t)z * BH * HH;
    const __nv_bfloat16* Al = g_hb_l + (size_t)z * BH * HH;
    const __nv_bfloat16* Bh = g_whh_h + (size_t)z * G4 * HH;
    const __nv_bfloat16* Bl = g_whh_l + (size_t)z * G4 * HH;
    float* C = g_gtmp + (size_t)z * BH * G4;

    int tid = threadIdx.x, wid = tid >> 5, lane = tid & 31;
    int wm = (wid & 1) * 64, wn = (wid >> 1) * 32;
    int bm = blockIdx.y * 128;
    int bn = blockIdx.x * 128;

    float acc[4][4][4];
    #pragma unroll
    for (int i = 0; i < 4; i++)
        #pragma unroll
        for (int j = 0; j < 4; j++)
            #pragma unroll
            for (int q = 0; q < 4; q++) acc[i][j][q] = 0.0f;

    gemm_core(Ah, Al, Bh, Bl, bm, bn, HH, HH / BK,
              smem_raw, tiles_u, tid, lane, wm, wn, acc);

    #pragma unroll
    for (int mt = 0; mt < 4; mt++) {
        #pragma unroll
        for (int nt = 0; nt < 4; nt++) {
            int row = bm + wm + mt * 16 + (lane >> 2);
            int col = bn + wn + nt * 8 + (lane & 3) * 2;
            float2 v0 = make_float2(acc[mt][nt][0], acc[mt][nt][1]);
            float2 v1 = make_float2(acc[mt][nt][2], acc[mt][nt][3]);
            *(float2*)(C + (size_t)row * G4 + col) = v0;
            *(float2*)(C + (size_t)(row + 8) * G4 + col) = v1;
        }
    }
}

// ---------------- K6: per-step LSTM pointwise (gate-interleaved float4 reads) ----------------
__global__ void lstm_point(int s) {
    int idx = blockIdx.x * blockDim.x + threadIdx.x;
    if (idx >= 2 * BH * HH) return;
    int dir = idx / (BH * HH);
    int r   = idx % (BH * HH);
    int n   = r / HH;
    int j   = r % HH;
    int t   = dir ? (TT - 1 - s) : s;

    float4 gx = *(const float4*)(g_gatesX + ((size_t)(n * TT + t)) * (2 * G4)
                                 + (size_t)dir * G4 + 4 * j);
    float gi = gx.x, gf = gx.y, gg = gx.z, go = gx.w;

    float c;
    if (s == 0) {
        c = sigf(gi) * tanhf(gg);
    } else {
        float4 gt = *(const float4*)(g_gtmp + (size_t)dir * BH * G4 + (size_t)n * G4 + 4 * j);
        gi += gt.x; gf += gt.y; gg += gt.z; go += gt.w;
        c = sigf(gf) * g_c[idx] + sigf(gi) * tanhf(gg);
    }
    float h = sigf(go) * tanhf(c);
    g_c[idx] = c;
    __nv_bfloat16 hi = __float2bfloat16(h);
    g_hb_h[idx] = hi;
    g_hb_l[idx] = __float2bfloat16(h - __bfloat162float(hi));
    g_compose[((size_t)n * TT + t) * DMODEL + dir * HH + j] = h;
}

// ---------------- K7: logits_rep (parallelized, deep ILP) ----------------
__global__ void logits_rep_kernel(const float* __restrict__ logits, const int* __restrict__ mask) {
    int b = blockIdx.x;
    int d = blockIdx.y * 128 + threadIdx.x;   // 6 blocks/batch, 128 threads each
    int tid = threadIdx.x;

    __shared__ unsigned char repl[SEQ];
    for (int i = tid; i < SEQ; i += blockDim.x) repl[i] = 0;
    __syncthreads();
    if (tid < 2 * HEADS) {
        int h = tid >> 1, half = tid & 1;
        int st = window_start(g_master[(b * HEADS + h) * 2 + half]);
        int base = half * LHALF + st;
        for (int k = 0; k < TT; k++) repl[base + k] = 1;
    }
    __syncthreads();
    for (int sPos = tid; sPos < SEQ; sPos += blockDim.x)
        repl[sPos] = (repl[sPos] && mask[b * SEQ + sPos] == 0) ? 1 : 0;
    __syncthreads();

    float a0 = 0.f, a1 = 0.f, a2 = 0.f, a3 = 0.f;
    const float* lp = logits + (size_t)b * SEQ * DMODEL + d;
    for (int sPos = 0; sPos < SEQ; sPos += 8) {
        float v0 = __ldg(lp + (size_t)(sPos + 0) * DMODEL);
        float v1 = __ldg(lp + (size_t)(sPos + 1) * DMODEL);
        float v2 = __ldg(lp + (size_t)(sPos + 2) * DMODEL);
        float v3 = __ldg(lp + (size_t)(sPos + 3) * DMODEL);
        float v4 = __ldg(lp + (size_t)(sPos + 4) * DMODEL);
        float v5 = __ldg(lp + (size_t)(sPos + 5) * DMODEL);
        float v6 = __ldg(lp + (size_t)(sPos + 6) * DMODEL);
        float v7 = __ldg(lp + (size_t)(sPos + 7) * DMODEL);
        a0 += repl[sPos]     ? EPSV : v0;
        a1 += repl[sPos + 1] ? EPSV : v1;
        a2 += repl[sPos + 2] ? EPSV : v2;
        a3 += repl[sPos + 3] ? EPSV : v3;
        a0 += repl[sPos + 4] ? EPSV : v4;
        a1 += repl[sPos + 5] ? EPSV : v5;
        a2 += repl[sPos + 6] ? EPSV : v6;
        a3 += repl[sPos + 7] ? EPSV : v7;
    }
    g_lrep[(size_t)b * DMODEL + d] = (a0 + a1 + a2 + a3) * (1.0f / (float)SEQ);
}

// ---------------- K8: final FC + softmax ----------------
__global__ void final_kernel(const float* __restrict__ fcw, const float* __restrict__ fcb,
                             float* __restrict__ out) {
    int b = blockIdx.x;
    int tid = threadIdx.x;
    const int NF = DMODEL * (HEADS + 1);
    float a0 = 0.0f, a1 = 0.0f;

    for (int j = tid; j < NF; j += 256) {
        float x;
        if (j < HEADS * DMODEL) {
            int h = j / DMODEL, d = j % DMODEL;
            int n = b * HEADS + h;
            const float* cp = g_compose + (size_t)n * TT * DMODEL + d;
            float s = 0.0f;
            #pragma unroll
            for (int t = 0; t < TT; t++) s += cp[(size_t)t * DMODEL];
            x = s * (1.0f / (float)TT);
        } else {
            x = g_lrep[(size_t)b * DMODEL + (j - HEADS * DMODEL)];
        }
        a0 += x * fcw[j];
        a1 += x * fcw[NF + j];
    }

    __shared__ float s0[256], s1[256];
    s0[tid] = a0; s1[tid] = a1;
    __syncthreads();
    for (int off = 128; off > 0; off >>= 1) {
        if (tid < off) { s0[tid] += s0[tid + off]; s1[tid] += s1[tid + off]; }
        __syncthreads();
    }
    if (tid == 0) {
        float l0 = s0[0] + fcb[0], l1 = s1[0] + fcb[1];
        float m = fmaxf(l0, l1);
        float e0 = expf(l0 - m), e1 = expf(l1 - m);
        float inv = 1.0f / (e0 + e1);
        out[b * 2 + 0] = e0 * inv;
        out[b * 2 + 1] = e1 * inv;
    }
}

// ---------------- launch ----------------
extern "C" void kernel_launch(void* const* d_in, const int* in_sizes, int n_in,
                              void* d_out, int out_size) {
    const int*   sents = (const int*)d_in[0];
    const float* att   = (const float*)d_in[1];
    const float* logits= (const float*)d_in[2];
    const int*   mask  = (const int*)d_in[3];
    const float* wih_f = (const float*)d_in[4];
    const float* whh_f = (const float*)d_in[5];
    const float* bih_f = (const float*)d_in[6];
    const float* bhh_f = (const float*)d_in[7];
    const float* wih_r = (const float*)d_in[8];
    const float* whh_r = (const float*)d_in[9];
    const float* bih_r = (const float*)d_in[10];
    const float* bhh_r = (const float*)d_in[11];
    const float* fc_w  = (const float*)d_in[12];
    const float* fc_b  = (const float*)d_in[13];
    float* out = (float*)d_out;

    cudaFuncSetAttribute(input_gemm_hmma, cudaFuncAttributeMaxDynamicSharedMemorySize, GM_SMEM);
    cudaFuncSetAttribute(rec_gemm_hmma, cudaFuncAttributeMaxDynamicSharedMemorySize, GM_SMEM);

    prep_kernel<<<(int)((PREP_TOTAL + 255) / 256), 256>>>(wih_f, wih_r, whh_f, whh_r,
                                                          bih_f, bhh_f, bih_r, bhh_r);
    masters_kernel<<<BH * 2, 256>>>(att, sents);
    build_slide<<<BH, 256>>>(logits, mask);

    // input GEMM: gatesX(2304x3072) = slide @ Wperm^T + bias (gate-interleaved cols)
    input_gemm_hmma<<<dim3(2 * G4 / 128, BH * TT / 128), 256, GM_SMEM>>>();

    for (int s = 0; s < TT; s++) {
        lstm_point<<<(2 * BH * HH + 255) / 256, 256>>>(s);
        if (s < TT - 1) {
            rec_gemm_hmma<<<dim3(G4 / 128, BH / 128, 2), 256, GM_SMEM>>>();
        }
    }

    logits_rep_kernel<<<dim3(BATCH, DMODEL / 128), 128>>>(logits, mask);
    final_kernel<<<BATCH, 256>>>(fc_w, fc_b, out);
}

// round 12
// speedup vs baseline: 1.6247x; 1.0910x over previous
#include <cuda_runtime.h>
#include <cuda_bf16.h>
#include <math.h>
#include <stdint.h>

// ---------------- problem constants ----------------
#define BATCH  32
#define HEADS  12
#define SEQ    512
#define LHALF  256
#define DMODEL 768
#define HH     384          // hidden per direction
#define G4     1536         // 4*HH gates
#define DIN    1536         // 2*DMODEL LSTM input
#define BH     384          // BATCH*HEADS
#define TT     6            // SLIDER
#define EPSV   1e-9f

// ---------------- device scratch (no allocs allowed) ----------------
__device__ int   g_master[BH * 2];
__device__ float g_gatesX[(size_t)BH * TT * 2 * G4];   // 2304 x 3072, gate-interleaved cols (4*j+gate), bias folded
__device__ float g_gtmp[(size_t)2 * BH * G4];          // per-step h @ whh^T (gate-interleaved cols)
__device__ float g_c[(size_t)2 * BH * HH];
__device__ float g_compose[(size_t)BH * TT * DMODEL];
__device__ float g_lrep[(size_t)BATCH * DMODEL];

// bf16 split operands (weights gate-interleaved: row' = 4*j + gate)
__device__ __nv_bfloat16 g_slide_h[(size_t)BH * TT * DIN];
__device__ __nv_bfloat16 g_slide_l[(size_t)BH * TT * DIN];
__device__ __nv_bfloat16 g_wih_h[(size_t)2 * G4 * DIN];
__device__ __nv_bfloat16 g_wih_l[(size_t)2 * G4 * DIN];
__device__ __nv_bfloat16 g_whh_h[(size_t)2 * G4 * HH];
__device__ __nv_bfloat16 g_whh_l[(size_t)2 * G4 * HH];
__device__ __nv_bfloat16 g_hb_h[(size_t)2 * BH * HH];     // [dir][n][j]
__device__ __nv_bfloat16 g_hb_l[(size_t)2 * BH * HH];
__device__ float g_bias[2 * G4];                          // gate-interleaved

// ---------------- PTX helpers (baseline PTX only) ----------------
__device__ __forceinline__ uint32_t smem_u32(const void* p) {
    uint32_t a;
    asm("{ .reg .u64 t; cvta.to.shared.u64 t, %1; cvt.u32.u64 %0, t; }" : "=r"(a) : "l"(p));
    return a;
}

#define CP_ASYNC16(sm, gm) \
    asm volatile("cp.async.cg.shared.global [%0], [%1], 16;" :: "r"(sm), "l"(gm) : "memory")
#define CP_COMMIT() asm volatile("cp.async.commit_group;" ::: "memory")
#define CP_WAIT0()  asm volatile("cp.async.wait_group 0;" ::: "memory")

#define LDSM_X4(r0, r1, r2, r3, addr) \
    asm volatile("ldmatrix.sync.aligned.m8n8.x4.shared.b16 {%0,%1,%2,%3}, [%4];" \
        : "=r"(r0), "=r"(r1), "=r"(r2), "=r"(r3) : "r"(addr))

#define MMA_BF16(c0, c1, c2, c3, a0, a1, a2, a3, b0, b1) \
    asm volatile("mma.sync.aligned.m16n8k16.row.col.f32.bf16.bf16.f32 " \
        "{%0,%1,%2,%3}, {%4,%5,%6,%7}, {%8,%9}, {%0,%1,%2,%3};" \
        : "+f"(c0), "+f"(c1), "+f"(c2), "+f"(c3) \
        : "r"(a0), "r"(a1), "r"(a2), "r"(a3), "r"(b0), "r"(b1))

// ---------------- helpers ----------------
__device__ __forceinline__ float sigf(float x) { return 1.0f / (1.0f + expf(-x)); }

__device__ __forceinline__ int window_start(int pos) {
    pos = min(max(pos, 1), LHALF - 2);
    int l = TT / 2;
    if (pos - TT / 2 <= 0) l = pos - 1;
    int r = TT - l;
    if (pos + r >= LHALF - 1) l = TT - (LHALF - pos - 2);
    return pos - l;
}

// ---------------- K1: masters (deep-MLP row sums) ----------------
__global__ void masters_kernel(const float* __restrict__ att, const int* __restrict__ sents) {
    int bid  = blockIdx.x;
    int half = bid & 1;
    int bh   = bid >> 1;
    int b    = bh / HEADS;

    __shared__ unsigned char seps[LHALF];
    __shared__ float rowsum[LHALF];

    int tid = threadIdx.x;
    {
        int j = half * LHALF + tid;
        seps[tid] = (sents[b * SEQ + j] == 102) ? 1 : 0;
    }
    __syncthreads();

    const float* base = att + ((size_t)bh * SEQ + (size_t)half * LHALF) * SEQ + (size_t)half * LHALF;

    int warp = tid >> 5, lane = tid & 31;
    #pragma unroll
    for (int rr = 0; rr < 32; rr += 4) {
        int row = warp * 32 + rr;
        const float4* r0 = (const float4*)(base + (size_t)(row + 0) * SEQ);
        const float4* r1 = (const float4*)(base + (size_t)(row + 1) * SEQ);
        const float4* r2 = (const float4*)(base + (size_t)(row + 2) * SEQ);
        const float4* r3 = (const float4*)(base + (size_t)(row + 3) * SEQ);
        float4 v0a = __ldg(r0 + lane), v0b = __ldg(r0 + lane + 32);
        float4 v1a = __ldg(r1 + lane), v1b = __ldg(r1 + lane + 32);
        float4 v2a = __ldg(r2 + lane), v2b = __ldg(r2 + lane + 32);
        float4 v3a = __ldg(r3 + lane), v3b = __ldg(r3 + lane + 32);

        int ja = lane * 4, jb = (lane + 32) * 4;
        float s0 = (seps[ja] ? EPSV : v0a.x) + (seps[ja+1] ? EPSV : v0a.y)
                 + (seps[ja+2] ? EPSV : v0a.z) + (seps[ja+3] ? EPSV : v0a.w)
                 + (seps[jb] ? EPSV : v0b.x) + (seps[jb+1] ? EPSV : v0b.y)
                 + (seps[jb+2] ? EPSV : v0b.z) + (seps[jb+3] ? EPSV : v0b.w);
        float s1 = (seps[ja] ? EPSV : v1a.x) + (seps[ja+1] ? EPSV : v1a.y)
                 + (seps[ja+2] ? EPSV : v1a.z) + (seps[ja+3] ? EPSV : v1a.w)
                 + (seps[jb] ? EPSV : v1b.x) + (seps[jb+1] ? EPSV : v1b.y)
                 + (seps[jb+2] ? EPSV : v1b.z) + (seps[jb+3] ? EPSV : v1b.w);
        float s2 = (seps[ja] ? EPSV : v2a.x) + (seps[ja+1] ? EPSV : v2a.y)
                 + (seps[ja+2] ? EPSV : v2a.z) + (seps[ja+3] ? EPSV : v2a.w)
                 + (seps[jb] ? EPSV : v2b.x) + (seps[jb+1] ? EPSV : v2b.y)
                 + (seps[jb+2] ? EPSV : v2b.z) + (seps[jb+3] ? EPSV : v2b.w);
        float s3 = (seps[ja] ? EPSV : v3a.x) + (seps[ja+1] ? EPSV : v3a.y)
                 + (seps[ja+2] ? EPSV : v3a.z) + (seps[ja+3] ? EPSV : v3a.w)
                 + (seps[jb] ? EPSV : v3b.x) + (seps[jb+1] ? EPSV : v3b.y)
                 + (seps[jb+2] ? EPSV : v3b.z) + (seps[jb+3] ? EPSV : v3b.w);

        #pragma unroll
        for (int off = 16; off > 0; off >>= 1) {
            s0 += __shfl_down_sync(0xffffffffu, s0, off);
            s1 += __shfl_down_sync(0xffffffffu, s1, off);
            s2 += __shfl_down_sync(0xffffffffu, s2, off);
            s3 += __shfl_down_sync(0xffffffffu, s3, off);
        }
        if (lane == 0) {
            rowsum[row]     = s0;
            rowsum[row + 1] = s1;
            rowsum[row + 2] = s2;
            rowsum[row + 3] = s3;
        }
    }
    __syncthreads();

    __shared__ float bv[LHALF];
    __shared__ int   bix[LHALF];
    bv[tid]  = rowsum[tid];
    bix[tid] = tid;
    __syncthreads();
    for (int off = 128; off > 0; off >>= 1) {
        if (tid < off) {
            float vo = bv[tid + off];
            int   io = bix[tid + off];
            if (vo > bv[tid] || (vo == bv[tid] && io < bix[tid])) { bv[tid] = vo; bix[tid] = io; }
        }
        __syncthreads();
    }
    if (tid == 0) g_master[bh * 2 + half] = bix[0];
}

// ---------------- K2: gather windows -> slide (bf16 hi/lo) ----------------
__global__ void build_slide(const float* __restrict__ logits, const int* __restrict__ mask) {
    int bh = blockIdx.x;
    int b  = bh / HEADS;
    __shared__ int sa, sb;
    if (threadIdx.x == 0) {
        sa = window_start(g_master[bh * 2 + 0]);
        sb = window_start(g_master[bh * 2 + 1]);
    }
    __syncthreads();

    for (int idx = threadIdx.x; idx < TT * DIN; idx += blockDim.x) {
        int t = idx / DIN, f = idx % DIN;
        float v;
        if (f < DMODEL) {
            int row = sa + t;
            v = (mask[b * SEQ + row] == 0) ? EPSV
                : logits[((size_t)b * SEQ + row) * DMODEL + f];
        } else {
            int row = LHALF + sb + t;
            v = (mask[b * SEQ + row] == 0) ? EPSV
                : logits[((size_t)b * SEQ + row) * DMODEL + (f - DMODEL)];
        }
        size_t off = (size_t)bh * (TT * DIN) + idx;
        __nv_bfloat16 hi = __float2bfloat16(v);
        g_slide_h[off] = hi;
        g_slide_l[off] = __float2bfloat16(v - __bfloat162float(hi));
    }
}

// ---------------- K3: fused prep (weight splits with gate interleave + bias) ----------------
#define NW ((size_t)G4 * DIN)    // 2359296
#define NH ((size_t)G4 * HH)     // 589824
#define PREP_TOTAL (2 * NW + 2 * NH + 2 * G4)

__global__ void prep_kernel(const float* __restrict__ wih_f, const float* __restrict__ wih_r,
                            const float* __restrict__ whh_f, const float* __restrict__ whh_r,
                            const float* __restrict__ bihf, const float* __restrict__ bhhf,
                            const float* __restrict__ bihr, const float* __restrict__ bhhr) {
    size_t i = (size_t)blockIdx.x * blockDim.x + threadIdx.x;
    if (i >= PREP_TOTAL) return;
    if (i < 2 * NW + 2 * NH) {
        const float* src;
        __nv_bfloat16 *dh, *dl;
        size_t off;
        int kdim;
        if (i < NW)               { src = wih_f; dh = g_wih_h;      dl = g_wih_l;      off = i;                kdim = DIN; }
        else if (i < 2 * NW)      { src = wih_r; dh = g_wih_h + NW; dl = g_wih_l + NW; off = i - NW;           kdim = DIN; }
        else if (i < 2 * NW + NH) { src = whh_f; dh = g_whh_h;      dl = g_whh_l;      off = i - 2 * NW;       kdim = HH;  }
        else                      { src = whh_r; dh = g_whh_h + NH; dl = g_whh_l + NH; off = i - 2 * NW - NH;  kdim = HH;  }
        size_t row = off / kdim, k = off % kdim;
        int gate = (int)(row / HH), j = (int)(row % HH);
        size_t drow = (size_t)(4 * j + gate);
        float x = src[off];
        __nv_bfloat16 hi = __float2bfloat16(x);
        dh[drow * kdim + k] = hi;
        dl[drow * kdim + k] = __float2bfloat16(x - __bfloat162float(hi));
    } else {
        size_t q = i - (2 * NW + 2 * NH);      // [0, 2*G4)
        int dir = (int)(q / G4);
        int r   = (int)(q % G4);
        int gate = r / HH, j = r % HH;
        float v = dir ? (bihr[r] + bhhr[r]) : (bihf[r] + bhhf[r]);
        g_bias[dir * G4 + 4 * j + gate] = v;
    }
}

// ---------------- GEMM core: tile 64(M) x 128(N), 2 CTAs/SM ----------------
// Chunk layout: Ah(8KB) | Al(8KB) | Bh(16KB) | Bl(16KB) = 48KB, double buffered.
#define BK          64
#define A_CHUNK     8192           // 64 rows x 128B
#define B_CHUNK     16384          // 128 rows x 128B
#define BUF_BYTES   (2 * A_CHUNK + 2 * B_CHUNK)   // 49152
#define GM_SMEM     (1024 + 2 * BUF_BYTES)        // 99328

__device__ __forceinline__ void gemm_core(
    const __nv_bfloat16* Ah, const __nv_bfloat16* Al,
    const __nv_bfloat16* Bh, const __nv_bfloat16* Bl,
    int bm, int bn, int K, int NC,
    char* smem_raw, uint32_t tiles_u,
    int tid, int lane, int wm, int wn,
    float acc[2][4][4])
{
    int Kd8 = K >> 3;

    auto load_chunk = [&](int c, int buf) {
        int k0 = c * BK;
        uint32_t bufu = tiles_u + buf * BUF_BYTES;
        // A operands: 64 rows, 512 uint4 each -> 2 per thread
        #pragma unroll
        for (int t2 = 0; t2 < 2; t2++) {
            const __nv_bfloat16* src = t2 ? Al : Ah;
            const uint4* gp = (const uint4*)(src + (size_t)bm * K + k0);
            uint32_t tb = bufu + t2 * A_CHUNK;
            #pragma unroll
            for (int i = 0; i < 2; i++) {
                int u = tid + i * 256;
                int r = u >> 3, c16 = u & 7;
                const uint4* ga = gp + (size_t)r * Kd8 + c16;
                uint32_t off = (uint32_t)(r * 128 + c16 * 16);
                uint32_t sw = off ^ ((off >> 3) & 0x70);
                CP_ASYNC16(tb + sw, ga);
            }
        }
        // B operands: 128 rows, 1024 uint4 each -> 4 per thread
        #pragma unroll
        for (int t2 = 0; t2 < 2; t2++) {
            const __nv_bfloat16* src = t2 ? Bl : Bh;
            const uint4* gp = (const uint4*)(src + (size_t)bn * K + k0);
            uint32_t tb = bufu + 2 * A_CHUNK + t2 * B_CHUNK;
            #pragma unroll
            for (int i = 0; i < 4; i++) {
                int u = tid + i * 256;
                int r = u >> 3, c16 = u & 7;
                const uint4* ga = gp + (size_t)r * Kd8 + c16;
                uint32_t off = (uint32_t)(r * 128 + c16 * 16);
                uint32_t sw = off ^ ((off >> 3) & 0x70);
                CP_ASYNC16(tb + sw, ga);
            }
        }
    };

    load_chunk(0, 0);
    CP_COMMIT();

    for (int c = 0; c < NC; c++) {
        CP_WAIT0();
        __syncthreads();
        if (c + 1 < NC) { load_chunk(c + 1, (c + 1) & 1); CP_COMMIT(); }

        uint32_t base = tiles_u + (c & 1) * BUF_BYTES;
        uint32_t ah_base = base;
        uint32_t al_base = base + A_CHUNK;
        uint32_t bh_base = base + 2 * A_CHUNK;
        uint32_t bl_base = base + 2 * A_CHUNK + B_CHUNK;

        #pragma unroll
        for (int ks = 0; ks < 4; ks++) {
            // hi fragments
            uint32_t a_h[2][4];
            #pragma unroll
            for (int mt = 0; mt < 2; mt++) {
                uint32_t r = wm + mt * 16 + (lane & 15);
                uint32_t coloff = ks * 32 + ((lane >> 4) & 1) * 16;
                uint32_t off = r * 128 + coloff;
                uint32_t sw = off ^ ((off >> 3) & 0x70);
                LDSM_X4(a_h[mt][0], a_h[mt][1], a_h[mt][2], a_h[mt][3], ah_base + sw);
            }
            uint32_t b_h[4][2];
            #pragma unroll
            for (int h = 0; h < 2; h++) {
                uint32_t r = wn + h * 16 + (lane & 7) + ((lane >> 4) << 3);
                uint32_t coloff = ks * 32 + ((lane >> 3) & 1) * 16;
                uint32_t off = r * 128 + coloff;
                uint32_t sw = off ^ ((off >> 3) & 0x70);
                uint32_t r0, r1, r2, r3;
                LDSM_X4(r0, r1, r2, r3, bh_base + sw);
                b_h[2 * h][0] = r0; b_h[2 * h][1] = r1;
                b_h[2 * h + 1][0] = r2; b_h[2 * h + 1][1] = r3;
            }
            // pass 1: Ah x Bh
            #pragma unroll
            for (int mt = 0; mt < 2; mt++)
                #pragma unroll
                for (int nt = 0; nt < 4; nt++)
                    MMA_BF16(acc[mt][nt][0], acc[mt][nt][1], acc[mt][nt][2], acc[mt][nt][3],
                             a_h[mt][0], a_h[mt][1], a_h[mt][2], a_h[mt][3],
                             b_h[nt][0], b_h[nt][1]);
            // lo fragments
            uint32_t a_l[2][4];
            #pragma unroll
            for (int mt = 0; mt < 2; mt++) {
                uint32_t r = wm + mt * 16 + (lane & 15);
                uint32_t coloff = ks * 32 + ((lane >> 4) & 1) * 16;
                uint32_t off = r * 128 + coloff;
                uint32_t sw = off ^ ((off >> 3) & 0x70);
                LDSM_X4(a_l[mt][0], a_l[mt][1], a_l[mt][2], a_l[mt][3], al_base + sw);
            }
            uint32_t b_l[4][2];
            #pragma unroll
            for (int h = 0; h < 2; h++) {
                uint32_t r = wn + h * 16 + (lane & 7) + ((lane >> 4) << 3);
                uint32_t coloff = ks * 32 + ((lane >> 3) & 1) * 16;
                uint32_t off = r * 128 + coloff;
                uint32_t sw = off ^ ((off >> 3) & 0x70);
                uint32_t r0, r1, r2, r3;
                LDSM_X4(r0, r1, r2, r3, bl_base + sw);
                b_l[2 * h][0] = r0; b_l[2 * h][1] = r1;
                b_l[2 * h + 1][0] = r2; b_l[2 * h + 1][1] = r3;
            }
            // pass 2: Ah x Bl
            #pragma unroll
            for (int mt = 0; mt < 2; mt++)
                #pragma unroll
                for (int nt = 0; nt < 4; nt++)
                    MMA_BF16(acc[mt][nt][0], acc[mt][nt][1], acc[mt][nt][2], acc[mt][nt][3],
                             a_h[mt][0], a_h[mt][1], a_h[mt][2], a_h[mt][3],
                             b_l[nt][0], b_l[nt][1]);
            // pass 3: Al x Bh
            #pragma unroll
            for (int mt = 0; mt < 2; mt++)
                #pragma unroll
                for (int nt = 0; nt < 4; nt++)
                    MMA_BF16(acc[mt][nt][0], acc[mt][nt][1], acc[mt][nt][2], acc[mt][nt][3],
                             a_l[mt][0], a_l[mt][1], a_l[mt][2], a_l[mt][3],
                             b_h[nt][0], b_h[nt][1]);
        }
        __syncthreads();
    }
}

// ---------------- K4: input GEMM (tile 64x128, 2 CTAs/SM) ----------------
__global__ __launch_bounds__(256, 2) void input_gemm_hmma() {
    extern __shared__ char smem_raw[];
    uint32_t smem_u = smem_u32(smem_raw);
    uint32_t tiles_u = (smem_u + 1023) & ~1023u;

    int tid = threadIdx.x, wid = tid >> 5, lane = tid & 31;
    int wm = (wid & 1) * 32, wn = (wid >> 1) * 32;
    int bm = blockIdx.y * 64;
    int bn = blockIdx.x * 128;

    float acc[2][4][4];
    #pragma unroll
    for (int i = 0; i < 2; i++)
        #pragma unroll
        for (int j = 0; j < 4; j++)
            #pragma unroll
            for (int q = 0; q < 4; q++) acc[i][j][q] = 0.0f;

    gemm_core(g_slide_h, g_slide_l, g_wih_h, g_wih_l,
              bm, bn, DIN, DIN / BK, smem_raw, tiles_u, tid, lane, wm, wn, acc);

    #pragma unroll
    for (int mt = 0; mt < 2; mt++) {
        #pragma unroll
        for (int nt = 0; nt < 4; nt++) {
            int row = bm + wm + mt * 16 + (lane >> 2);
            int col = bn + wn + nt * 8 + (lane & 3) * 2;
            float b0 = g_bias[col], b1 = g_bias[col + 1];
            float2 v0 = make_float2(acc[mt][nt][0] + b0, acc[mt][nt][1] + b1);
            float2 v1 = make_float2(acc[mt][nt][2] + b0, acc[mt][nt][3] + b1);
            *(float2*)(g_gatesX + (size_t)row * (2 * G4) + col) = v0;
            *(float2*)(g_gatesX + (size_t)(row + 8) * (2 * G4) + col) = v1;
        }
    }
}

// ---------------- K5: recurrent GEMM  gtmp[dir] = h[dir] @ whh[dir]^T ----------------
__global__ __launch_bounds__(256, 2) void rec_gemm_hmma() {
    extern __shared__ char smem_raw[];
    uint32_t smem_u = smem_u32(smem_raw);
    uint32_t tiles_u = (smem_u + 1023) & ~1023u;

    int z = blockIdx.z;
    const __nv_bfloat16* Ah = g_hb_h + (size_t)z * BH * HH;
    const __nv_bfloat16* Al = g_hb_l + (size_t)z * BH * HH;
    const __nv_bfloat16* Bh = g_whh_h + (size_t)z * G4 * HH;
    const __nv_bfloat16* Bl = g_whh_l + (size_t)z * G4 * HH;
    float* C = g_gtmp + (size_t)z * BH * G4;

    int tid = threadIdx.x, wid = tid >> 5, lane = tid & 31;
    int wm = (wid & 1) * 32, wn = (wid >> 1) * 32;
    int bm = blockIdx.y * 64;
    int bn = blockIdx.x * 128;

    float acc[2][4][4];
    #pragma unroll
    for (int i = 0; i < 2; i++)
        #pragma unroll
        for (int j = 0; j < 4; j++)
            #pragma unroll
            for (int q = 0; q < 4; q++) acc[i][j][q] = 0.0f;

    gemm_core(Ah, Al, Bh, Bl, bm, bn, HH, HH / BK,
              smem_raw, tiles_u, tid, lane, wm, wn, acc);

    #pragma unroll
    for (int mt = 0; mt < 2; mt++) {
        #pragma unroll
        for (int nt = 0; nt < 4; nt++) {
            int row = bm + wm + mt * 16 + (lane >> 2);
            int col = bn + wn + nt * 8 + (lane & 3) * 2;
            float2 v0 = make_float2(acc[mt][nt][0], acc[mt][nt][1]);
            float2 v1 = make_float2(acc[mt][nt][2], acc[mt][nt][3]);
            *(float2*)(C + (size_t)row * G4 + col) = v0;
            *(float2*)(C + (size_t)(row + 8) * G4 + col) = v1;
        }
    }
}

// ---------------- K6: per-step LSTM pointwise (gate-interleaved float4 reads) ----------------
__global__ void lstm_point(int s) {
    int idx = blockIdx.x * blockDim.x + threadIdx.x;
    if (idx >= 2 * BH * HH) return;
    int dir = idx / (BH * HH);
    int r   = idx % (BH * HH);
    int n   = r / HH;
    int j   = r % HH;
    int t   = dir ? (TT - 1 - s) : s;

    float4 gx = *(const float4*)(g_gatesX + ((size_t)(n * TT + t)) * (2 * G4)
                                 + (size_t)dir * G4 + 4 * j);
    float gi = gx.x, gf = gx.y, gg = gx.z, go = gx.w;

    float c;
    if (s == 0) {
        c = sigf(gi) * tanhf(gg);
    } else {
        float4 gt = *(const float4*)(g_gtmp + (size_t)dir * BH * G4 + (size_t)n * G4 + 4 * j);
        gi += gt.x; gf += gt.y; gg += gt.z; go += gt.w;
        c = sigf(gf) * g_c[idx] + sigf(gi) * tanhf(gg);
    }
    float h = sigf(go) * tanhf(c);
    g_c[idx] = c;
    __nv_bfloat16 hi = __float2bfloat16(h);
    g_hb_h[idx] = hi;
    g_hb_l[idx] = __float2bfloat16(h - __bfloat162float(hi));
    g_compose[((size_t)n * TT + t) * DMODEL + dir * HH + j] = h;
}

// ---------------- K7: logits_rep (parallelized, deep ILP) ----------------
__global__ void logits_rep_kernel(const float* __restrict__ logits, const int* __restrict__ mask) {
    int b = blockIdx.x;
    int d = blockIdx.y * 128 + threadIdx.x;
    int tid = threadIdx.x;

    __shared__ unsigned char repl[SEQ];
    for (int i = tid; i < SEQ; i += blockDim.x) repl[i] = 0;
    __syncthreads();
    if (tid < 2 * HEADS) {
        int h = tid >> 1, half = tid & 1;
        int st = window_start(g_master[(b * HEADS + h) * 2 + half]);
        int base = half * LHALF + st;
        for (int k = 0; k < TT; k++) repl[base + k] = 1;
    }
    __syncthreads();
    for (int sPos = tid; sPos < SEQ; sPos += blockDim.x)
        repl[sPos] = (repl[sPos] && mask[b * SEQ + sPos] == 0) ? 1 : 0;
    __syncthreads();

    float a0 = 0.f, a1 = 0.f, a2 = 0.f, a3 = 0.f;
    const float* lp = logits + (size_t)b * SEQ * DMODEL + d;
    for (int sPos = 0; sPos < SEQ; sPos += 8) {
        float v0 = __ldg(lp + (size_t)(sPos + 0) * DMODEL);
        float v1 = __ldg(lp + (size_t)(sPos + 1) * DMODEL);
        float v2 = __ldg(lp + (size_t)(sPos + 2) * DMODEL);
        float v3 = __ldg(lp + (size_t)(sPos + 3) * DMODEL);
        float v4 = __ldg(lp + (size_t)(sPos + 4) * DMODEL);
        float v5 = __ldg(lp + (size_t)(sPos + 5) * DMODEL);
        float v6 = __ldg(lp + (size_t)(sPos + 6) * DMODEL);
        float v7 = __ldg(lp + (size_t)(sPos + 7) * DMODEL);
        a0 += repl[sPos]     ? EPSV : v0;
        a1 += repl[sPos + 1] ? EPSV : v1;
        a2 += repl[sPos + 2] ? EPSV : v2;
        a3 += repl[sPos + 3] ? EPSV : v3;
        a0 += repl[sPos + 4] ? EPSV : v4;
        a1 += repl[sPos + 5] ? EPSV : v5;
        a2 += repl[sPos + 6] ? EPSV : v6;
        a3 += repl[sPos + 7] ? EPSV : v7;
    }
    g_lrep[(size_t)b * DMODEL + d] = (a0 + a1 + a2 + a3) * (1.0f / (float)SEQ);
}

// ---------------- K8: final FC + softmax ----------------
__global__ void final_kernel(const float* __restrict__ fcw, const float* __restrict__ fcb,
                             float* __restrict__ out) {
    int b = blockIdx.x;
    int tid = threadIdx.x;
    const int NF = DMODEL * (HEADS + 1);
    float a0 = 0.0f, a1 = 0.0f;

    for (int j = tid; j < NF; j += 256) {
        float x;
        if (j < HEADS * DMODEL) {
            int h = j / DMODEL, d = j % DMODEL;
            int n = b * HEADS + h;
            const float* cp = g_compose + (size_t)n * TT * DMODEL + d;
            float s = 0.0f;
            #pragma unroll
            for (int t = 0; t < TT; t++) s += cp[(size_t)t * DMODEL];
            x = s * (1.0f / (float)TT);
        } else {
            x = g_lrep[(size_t)b * DMODEL + (j - HEADS * DMODEL)];
        }
        a0 += x * fcw[j];
        a1 += x * fcw[NF + j];
    }

    __shared__ float s0[256], s1[256];
    s0[tid] = a0; s1[tid] = a1;
    __syncthreads();
    for (int off = 128; off > 0; off >>= 1) {
        if (tid < off) { s0[tid] += s0[tid + off]; s1[tid] += s1[tid + off]; }
        __syncthreads();
    }
    if (tid == 0) {
        float l0 = s0[0] + fcb[0], l1 = s1[0] + fcb[1];
        float m = fmaxf(l0, l1);
        float e0 = expf(l0 - m), e1 = expf(l1 - m);
        float inv = 1.0f / (e0 + e1);
        out[b * 2 + 0] = e0 * inv;
        out[b * 2 + 1] = e1 * inv;
    }
}

// ---------------- launch ----------------
extern "C" void kernel_launch(void* const* d_in, const int* in_sizes, int n_in,
                              void* d_out, int out_size) {
    const int*   sents = (const int*)d_in[0];
    const float* att   = (const float*)d_in[1];
    const float* logits= (const float*)d_in[2];
    const int*   mask  = (const int*)d_in[3];
    const float* wih_f = (const float*)d_in[4];
    const float* whh_f = (const float*)d_in[5];
    const float* bih_f = (const float*)d_in[6];
    const float* bhh_f = (const float*)d_in[7];
    const float* wih_r = (const float*)d_in[8];
    const float* whh_r = (const float*)d_in[9];
    const float* bih_r = (const float*)d_in[10];
    const float* bhh_r = (const float*)d_in[11];
    const float* fc_w  = (const float*)d_in[12];
    const float* fc_b  = (const float*)d_in[13];
    float* out = (float*)d_out;

    cudaFuncSetAttribute(input_gemm_hmma, cudaFuncAttributeMaxDynamicSharedMemorySize, GM_SMEM);
    cudaFuncSetAttribute(rec_gemm_hmma, cudaFuncAttributeMaxDynamicSharedMemorySize, GM_SMEM);

    prep_kernel<<<(int)((PREP_TOTAL + 255) / 256), 256>>>(wih_f, wih_r, whh_f, whh_r,
                                                          bih_f, bhh_f, bih_r, bhh_r);
    masters_kernel<<<BH * 2, 256>>>(att, sents);
    build_slide<<<BH, 256>>>(logits, mask);

    // input GEMM: gatesX(2304x3072) = slide @ Wperm^T + bias
    input_gemm_hmma<<<dim3(2 * G4 / 128, BH * TT / 64), 256, GM_SMEM>>>();

    for (int s = 0; s < TT; s++) {
        lstm_point<<<(2 * BH * HH + 255) / 256, 256>>>(s);
        if (s < TT - 1) {
            rec_gemm_hmma<<<dim3(G4 / 128, BH / 64, 2), 256, GM_SMEM>>>();
        }
    }

    logits_rep_kernel<<<dim3(BATCH, DMODEL / 128), 128>>>(logits, mask);
    final_kernel<<<BATCH, 256>>>(fc_w, fc_b, out);
}

// round 13
// speedup vs baseline: 1.9396x; 1.1938x over previous
#include <cuda_runtime.h>
#include <cuda_fp16.h>
#include <math.h>
#include <stdint.h>

// ---------------- problem constants ----------------
#define BATCH  32
#define HEADS  12
#define SEQ    512
#define LHALF  256
#define DMODEL 768
#define HH     384          // hidden per direction
#define G4     1536         // 4*HH gates
#define DIN    1536         // 2*DMODEL LSTM input
#define BH     384          // BATCH*HEADS
#define TT     6            // SLIDER
#define EPSV   1e-9f

// ---------------- device scratch (no allocs allowed) ----------------
__device__ int   g_master[BH * 2];
__device__ float g_gatesX[(size_t)BH * TT * 2 * G4];   // 2304 x 3072, gate-interleaved cols (4*j+gate), bias folded
__device__ float g_gtmp[(size_t)2 * BH * G4];          // per-step h @ whh^T (gate-interleaved cols)
__device__ float g_c[(size_t)2 * BH * HH];
__device__ float g_compose[(size_t)BH * TT * DMODEL];
__device__ float g_lrep[(size_t)BATCH * DMODEL];

// fp16 operands: activations split hi/lo, weights single fp16 (gate-interleaved rows: 4*j+gate)
__device__ __half g_slide_h[(size_t)BH * TT * DIN];
__device__ __half g_slide_l[(size_t)BH * TT * DIN];
__device__ __half g_wih[(size_t)2 * G4 * DIN];
__device__ __half g_whh[(size_t)2 * G4 * HH];
__device__ __half g_hb_h[(size_t)2 * BH * HH];     // [dir][n][j]
__device__ __half g_hb_l[(size_t)2 * BH * HH];
__device__ float g_bias[2 * G4];                   // gate-interleaved

// ---------------- PTX helpers (baseline PTX only) ----------------
__device__ __forceinline__ uint32_t smem_u32(const void* p) {
    uint32_t a;
    asm("{ .reg .u64 t; cvta.to.shared.u64 t, %1; cvt.u32.u64 %0, t; }" : "=r"(a) : "l"(p));
    return a;
}

#define CP_ASYNC16(sm, gm) \
    asm volatile("cp.async.cg.shared.global [%0], [%1], 16;" :: "r"(sm), "l"(gm) : "memory")
#define CP_COMMIT() asm volatile("cp.async.commit_group;" ::: "memory")
#define CP_WAIT0()  asm volatile("cp.async.wait_group 0;" ::: "memory")

#define LDSM_X4(r0, r1, r2, r3, addr) \
    asm volatile("ldmatrix.sync.aligned.m8n8.x4.shared.b16 {%0,%1,%2,%3}, [%4];" \
        : "=r"(r0), "=r"(r1), "=r"(r2), "=r"(r3) : "r"(addr))

#define MMA_F16(c0, c1, c2, c3, a0, a1, a2, a3, b0, b1) \
    asm volatile("mma.sync.aligned.m16n8k16.row.col.f32.f16.f16.f32 " \
        "{%0,%1,%2,%3}, {%4,%5,%6,%7}, {%8,%9}, {%0,%1,%2,%3};" \
        : "+f"(c0), "+f"(c1), "+f"(c2), "+f"(c3) \
        : "r"(a0), "r"(a1), "r"(a2), "r"(a3), "r"(b0), "r"(b1))

// ---------------- helpers ----------------
__device__ __forceinline__ float sigf(float x) { return 1.0f / (1.0f + expf(-x)); }

__device__ __forceinline__ int window_start(int pos) {
    pos = min(max(pos, 1), LHALF - 2);
    int l = TT / 2;
    if (pos - TT / 2 <= 0) l = pos - 1;
    int r = TT - l;
    if (pos + r >= LHALF - 1) l = TT - (LHALF - pos - 2);
    return pos - l;
}

// ---------------- K1: masters (deep-MLP row sums) ----------------
__global__ void masters_kernel(const float* __restrict__ att, const int* __restrict__ sents) {
    int bid  = blockIdx.x;
    int half = bid & 1;
    int bh   = bid >> 1;
    int b    = bh / HEADS;

    __shared__ unsigned char seps[LHALF];
    __shared__ float rowsum[LHALF];

    int tid = threadIdx.x;
    {
        int j = half * LHALF + tid;
        seps[tid] = (sents[b * SEQ + j] == 102) ? 1 : 0;
    }
    __syncthreads();

    const float* base = att + ((size_t)bh * SEQ + (size_t)half * LHALF) * SEQ + (size_t)half * LHALF;

    int warp = tid >> 5, lane = tid & 31;
    #pragma unroll
    for (int rr = 0; rr < 32; rr += 4) {
        int row = warp * 32 + rr;
        const float4* r0 = (const float4*)(base + (size_t)(row + 0) * SEQ);
        const float4* r1 = (const float4*)(base + (size_t)(row + 1) * SEQ);
        const float4* r2 = (const float4*)(base + (size_t)(row + 2) * SEQ);
        const float4* r3 = (const float4*)(base + (size_t)(row + 3) * SEQ);
        float4 v0a = __ldg(r0 + lane), v0b = __ldg(r0 + lane + 32);
        float4 v1a = __ldg(r1 + lane), v1b = __ldg(r1 + lane + 32);
        float4 v2a = __ldg(r2 + lane), v2b = __ldg(r2 + lane + 32);
        float4 v3a = __ldg(r3 + lane), v3b = __ldg(r3 + lane + 32);

        int ja = lane * 4, jb = (lane + 32) * 4;
        float s0 = (seps[ja] ? EPSV : v0a.x) + (seps[ja+1] ? EPSV : v0a.y)
                 + (seps[ja+2] ? EPSV : v0a.z) + (seps[ja+3] ? EPSV : v0a.w)
                 + (seps[jb] ? EPSV : v0b.x) + (seps[jb+1] ? EPSV : v0b.y)
                 + (seps[jb+2] ? EPSV : v0b.z) + (seps[jb+3] ? EPSV : v0b.w);
        float s1 = (seps[ja] ? EPSV : v1a.x) + (seps[ja+1] ? EPSV : v1a.y)
                 + (seps[ja+2] ? EPSV : v1a.z) + (seps[ja+3] ? EPSV : v1a.w)
                 + (seps[jb] ? EPSV : v1b.x) + (seps[jb+1] ? EPSV : v1b.y)
                 + (seps[jb+2] ? EPSV : v1b.z) + (seps[jb+3] ? EPSV : v1b.w);
        float s2 = (seps[ja] ? EPSV : v2a.x) + (seps[ja+1] ? EPSV : v2a.y)
                 + (seps[ja+2] ? EPSV : v2a.z) + (seps[ja+3] ? EPSV : v2a.w)
                 + (seps[jb] ? EPSV : v2b.x) + (seps[jb+1] ? EPSV : v2b.y)
                 + (seps[jb+2] ? EPSV : v2b.z) + (seps[jb+3] ? EPSV : v2b.w);
        float s3 = (seps[ja] ? EPSV : v3a.x) + (seps[ja+1] ? EPSV : v3a.y)
                 + (seps[ja+2] ? EPSV : v3a.z) + (seps[ja+3] ? EPSV : v3a.w)
                 + (seps[jb] ? EPSV : v3b.x) + (seps[jb+1] ? EPSV : v3b.y)
                 + (seps[jb+2] ? EPSV : v3b.z) + (seps[jb+3] ? EPSV : v3b.w);

        #pragma unroll
        for (int off = 16; off > 0; off >>= 1) {
            s0 += __shfl_down_sync(0xffffffffu, s0, off);
            s1 += __shfl_down_sync(0xffffffffu, s1, off);
            s2 += __shfl_down_sync(0xffffffffu, s2, off);
            s3 += __shfl_down_sync(0xffffffffu, s3, off);
        }
        if (lane == 0) {
            rowsum[row]     = s0;
            rowsum[row + 1] = s1;
            rowsum[row + 2] = s2;
            rowsum[row + 3] = s3;
        }
    }
    __syncthreads();

    __shared__ float bv[LHALF];
    __shared__ int   bix[LHALF];
    bv[tid]  = rowsum[tid];
    bix[tid] = tid;
    __syncthreads();
    for (int off = 128; off > 0; off >>= 1) {
        if (tid < off) {
            float vo = bv[tid + off];
            int   io = bix[tid + off];
            if (vo > bv[tid] || (vo == bv[tid] && io < bix[tid])) { bv[tid] = vo; bix[tid] = io; }
        }
        __syncthreads();
    }
    if (tid == 0) g_master[bh * 2 + half] = bix[0];
}

// ---------------- K2: gather windows -> slide (fp16 hi/lo) ----------------
__global__ void build_slide(const float* __restrict__ logits, const int* __restrict__ mask) {
    int bh = blockIdx.x;
    int b  = bh / HEADS;
    __shared__ int sa, sb;
    if (threadIdx.x == 0) {
        sa = window_start(g_master[bh * 2 + 0]);
        sb = window_start(g_master[bh * 2 + 1]);
    }
    __syncthreads();

    for (int idx = threadIdx.x; idx < TT * DIN; idx += blockDim.x) {
        int t = idx / DIN, f = idx % DIN;
        float v;
        if (f < DMODEL) {
            int row = sa + t;
            v = (mask[b * SEQ + row] == 0) ? EPSV
                : logits[((size_t)b * SEQ + row) * DMODEL + f];
        } else {
            int row = LHALF + sb + t;
            v = (mask[b * SEQ + row] == 0) ? EPSV
                : logits[((size_t)b * SEQ + row) * DMODEL + (f - DMODEL)];
        }
        size_t off = (size_t)bh * (TT * DIN) + idx;
        __half hi = __float2half(v);
        g_slide_h[off] = hi;
        g_slide_l[off] = __float2half(v - __half2float(hi));
    }
}

// ---------------- K3: fused prep (fp16 weights with gate interleave + bias) ----------------
// Output row within each direction block: row' = 4*j + gate, where src row = gate*HH + j.
#define NW ((size_t)G4 * DIN)    // 2359296
#define NH ((size_t)G4 * HH)     // 589824
#define PREP_TOTAL (2 * NW + 2 * NH + 2 * G4)

__global__ void prep_kernel(const float* __restrict__ wih_f, const float* __restrict__ wih_r,
                            const float* __restrict__ whh_f, const float* __restrict__ whh_r,
                            const float* __restrict__ bihf, const float* __restrict__ bhhf,
                            const float* __restrict__ bihr, const float* __restrict__ bhhr) {
    size_t i = (size_t)blockIdx.x * blockDim.x + threadIdx.x;
    if (i >= PREP_TOTAL) return;
    if (i < 2 * NW + 2 * NH) {
        const float* src;
        __half* dh;
        size_t off;
        int kdim;
        if (i < NW)               { src = wih_f; dh = g_wih;      off = i;                kdim = DIN; }
        else if (i < 2 * NW)      { src = wih_r; dh = g_wih + NW; off = i - NW;           kdim = DIN; }
        else if (i < 2 * NW + NH) { src = whh_f; dh = g_whh;      off = i - 2 * NW;       kdim = HH;  }
        else                      { src = whh_r; dh = g_whh + NH; off = i - 2 * NW - NH;  kdim = HH;  }
        size_t row = off / kdim, k = off % kdim;
        int gate = (int)(row / HH), j = (int)(row % HH);
        size_t drow = (size_t)(4 * j + gate);
        dh[drow * kdim + k] = __float2half(src[off]);
    } else {
        size_t q = i - (2 * NW + 2 * NH);      // [0, 2*G4)
        int dir = (int)(q / G4);
        int r   = (int)(q % G4);
        int gate = r / HH, j = r % HH;
        float v = dir ? (bihr[r] + bhhr[r]) : (bihf[r] + bhhf[r]);
        g_bias[dir * G4 + 4 * j + gate] = v;
    }
}

// ---------------- GEMM core: tile 64(M) x 128(N), fp16 2-product, 2 CTAs/SM ----------------
// Chunk layout: Ah(8KB) | Al(8KB) | B(16KB) = 32KB, double buffered.
#define BK          64
#define A_CHUNK     8192           // 64 rows x 128B
#define B_CHUNK     16384          // 128 rows x 128B
#define BUF_BYTES   (2 * A_CHUNK + B_CHUNK)   // 32768
#define GM_SMEM     (1024 + 2 * BUF_BYTES)    // 66560

__device__ __forceinline__ void gemm_core(
    const __half* Ah, const __half* Al, const __half* B,
    int bm, int bn, int K, int NC,
    char* smem_raw, uint32_t tiles_u,
    int tid, int lane, int wm, int wn,
    float acc[2][4][4])
{
    int Kd8 = K >> 3;

    auto load_chunk = [&](int c, int buf) {
        int k0 = c * BK;
        uint32_t bufu = tiles_u + buf * BUF_BYTES;
        // A operands (hi, lo): 64 rows, 512 uint4 each -> 2 per thread
        #pragma unroll
        for (int t2 = 0; t2 < 2; t2++) {
            const __half* src = t2 ? Al : Ah;
            const uint4* gp = (const uint4*)(src + (size_t)bm * K + k0);
            uint32_t tb = bufu + t2 * A_CHUNK;
            #pragma unroll
            for (int i = 0; i < 2; i++) {
                int u = tid + i * 256;
                int r = u >> 3, c16 = u & 7;
                const uint4* ga = gp + (size_t)r * Kd8 + c16;
                uint32_t off = (uint32_t)(r * 128 + c16 * 16);
                uint32_t sw = off ^ ((off >> 3) & 0x70);
                CP_ASYNC16(tb + sw, ga);
            }
        }
        // B operand: 128 rows, 1024 uint4 -> 4 per thread
        {
            const uint4* gp = (const uint4*)(B + (size_t)bn * K + k0);
            uint32_t tb = bufu + 2 * A_CHUNK;
            #pragma unroll
            for (int i = 0; i < 4; i++) {
                int u = tid + i * 256;
                int r = u >> 3, c16 = u & 7;
                const uint4* ga = gp + (size_t)r * Kd8 + c16;
                uint32_t off = (uint32_t)(r * 128 + c16 * 16);
                uint32_t sw = off ^ ((off >> 3) & 0x70);
                CP_ASYNC16(tb + sw, ga);
            }
        }
    };

    load_chunk(0, 0);
    CP_COMMIT();

    for (int c = 0; c < NC; c++) {
        CP_WAIT0();
        __syncthreads();
        if (c + 1 < NC) { load_chunk(c + 1, (c + 1) & 1); CP_COMMIT(); }

        uint32_t base = tiles_u + (c & 1) * BUF_BYTES;
        uint32_t ah_base = base;
        uint32_t al_base = base + A_CHUNK;
        uint32_t b_base  = base + 2 * A_CHUNK;

        #pragma unroll
        for (int ks = 0; ks < 4; ks++) {
            uint32_t a_h[2][4], a_l[2][4];
            #pragma unroll
            for (int mt = 0; mt < 2; mt++) {
                uint32_t r = wm + mt * 16 + (lane & 15);
                uint32_t coloff = ks * 32 + ((lane >> 4) & 1) * 16;
                uint32_t off = r * 128 + coloff;
                uint32_t sw = off ^ ((off >> 3) & 0x70);
                LDSM_X4(a_h[mt][0], a_h[mt][1], a_h[mt][2], a_h[mt][3], ah_base + sw);
                LDSM_X4(a_l[mt][0], a_l[mt][1], a_l[mt][2], a_l[mt][3], al_base + sw);
            }
            uint32_t b[4][2];
            #pragma unroll
            for (int h = 0; h < 2; h++) {
                uint32_t r = wn + h * 16 + (lane & 7) + ((lane >> 4) << 3);
                uint32_t coloff = ks * 32 + ((lane >> 3) & 1) * 16;
                uint32_t off = r * 128 + coloff;
                uint32_t sw = off ^ ((off >> 3) & 0x70);
                uint32_t r0, r1, r2, r3;
                LDSM_X4(r0, r1, r2, r3, b_base + sw);
                b[2 * h][0] = r0; b[2 * h][1] = r1;
                b[2 * h + 1][0] = r2; b[2 * h + 1][1] = r3;
            }
            // pass 1: Ah x B
            #pragma unroll
            for (int mt = 0; mt < 2; mt++)
                #pragma unroll
                for (int nt = 0; nt < 4; nt++)
                    MMA_F16(acc[mt][nt][0], acc[mt][nt][1], acc[mt][nt][2], acc[mt][nt][3],
                            a_h[mt][0], a_h[mt][1], a_h[mt][2], a_h[mt][3],
                            b[nt][0], b[nt][1]);
            // pass 2: Al x B
            #pragma unroll
            for (int mt = 0; mt < 2; mt++)
                #pragma unroll
                for (int nt = 0; nt < 4; nt++)
                    MMA_F16(acc[mt][nt][0], acc[mt][nt][1], acc[mt][nt][2], acc[mt][nt][3],
                            a_l[mt][0], a_l[mt][1], a_l[mt][2], a_l[mt][3],
                            b[nt][0], b[nt][1]);
        }
        __syncthreads();
    }
}

// ---------------- K4: input GEMM (tile 64x128, 2 CTAs/SM) ----------------
__global__ __launch_bounds__(256, 2) void input_gemm_hmma() {
    extern __shared__ char smem_raw[];
    uint32_t smem_u = smem_u32(smem_raw);
    uint32_t tiles_u = (smem_u + 1023) & ~1023u;

    int tid = threadIdx.x, wid = tid >> 5, lane = tid & 31;
    int wm = (wid & 1) * 32, wn = (wid >> 1) * 32;
    int bm = blockIdx.y * 64;
    int bn = blockIdx.x * 128;

    float acc[2][4][4];
    #pragma unroll
    for (int i = 0; i < 2; i++)
        #pragma unroll
        for (int j = 0; j < 4; j++)
            #pragma unroll
            for (int q = 0; q < 4; q++) acc[i][j][q] = 0.0f;

    gemm_core(g_slide_h, g_slide_l, g_wih,
              bm, bn, DIN, DIN / BK, smem_raw, tiles_u, tid, lane, wm, wn, acc);

    #pragma unroll
    for (int mt = 0; mt < 2; mt++) {
        #pragma unroll
        for (int nt = 0; nt < 4; nt++) {
            int row = bm + wm + mt * 16 + (lane >> 2);
            int col = bn + wn + nt * 8 + (lane & 3) * 2;
            float b0 = g_bias[col], b1 = g_bias[col + 1];
            float2 v0 = make_float2(acc[mt][nt][0] + b0, acc[mt][nt][1] + b1);
            float2 v1 = make_float2(acc[mt][nt][2] + b0, acc[mt][nt][3] + b1);
            *(float2*)(g_gatesX + (size_t)row * (2 * G4) + col) = v0;
            *(float2*)(g_gatesX + (size_t)(row + 8) * (2 * G4) + col) = v1;
        }
    }
}

// ---------------- K5: recurrent GEMM  gtmp[dir] = h[dir] @ whh[dir]^T ----------------
__global__ __launch_bounds__(256, 2) void rec_gemm_hmma() {
    extern __shared__ char smem_raw[];
    uint32_t smem_u = smem_u32(smem_raw);
    uint32_t tiles_u = (smem_u + 1023) & ~1023u;

    int z = blockIdx.z;
    const __half* Ah = g_hb_h + (size_t)z * BH * HH;
    const __half* Al = g_hb_l + (size_t)z * BH * HH;
    const __half* B  = g_whh + (size_t)z * G4 * HH;
    float* C = g_gtmp + (size_t)z * BH * G4;

    int tid = threadIdx.x, wid = tid >> 5, lane = tid & 31;
    int wm = (wid & 1) * 32, wn = (wid >> 1) * 32;
    int bm = blockIdx.y * 64;
    int bn = blockIdx.x * 128;

    float acc[2][4][4];
    #pragma unroll
    for (int i = 0; i < 2; i++)
        #pragma unroll
        for (int j = 0; j < 4; j++)
            #pragma unroll
            for (int q = 0; q < 4; q++) acc[i][j][q] = 0.0f;

    gemm_core(Ah, Al, B, bm, bn, HH, HH / BK,
              smem_raw, tiles_u, tid, lane, wm, wn, acc);

    #pragma unroll
    for (int mt = 0; mt < 2; mt++) {
        #pragma unroll
        for (int nt = 0; nt < 4; nt++) {
            int row = bm + wm + mt * 16 + (lane >> 2);
            int col = bn + wn + nt * 8 + (lane & 3) * 2;
            float2 v0 = make_float2(acc[mt][nt][0], acc[mt][nt][1]);
            float2 v1 = make_float2(acc[mt][nt][2], acc[mt][nt][3]);
            *(float2*)(C + (size_t)row * G4 + col) = v0;
            *(float2*)(C + (size_t)(row + 8) * G4 + col) = v1;
        }
    }
}

// ---------------- K6: per-step LSTM pointwise (gate-interleaved float4 reads) ----------------
__global__ void lstm_point(int s) {
    int idx = blockIdx.x * blockDim.x + threadIdx.x;
    if (idx >= 2 * BH * HH) return;
    int dir = idx / (BH * HH);
    int r   = idx % (BH * HH);
    int n   = r / HH;
    int j   = r % HH;
    int t   = dir ? (TT - 1 - s) : s;

    float4 gx = *(const float4*)(g_gatesX + ((size_t)(n * TT + t)) * (2 * G4)
                                 + (size_t)dir * G4 + 4 * j);
    float gi = gx.x, gf = gx.y, gg = gx.z, go = gx.w;

    float c;
    if (s == 0) {
        c = sigf(gi) * tanhf(gg);
    } else {
        float4 gt = *(const float4*)(g_gtmp + (size_t)dir * BH * G4 + (size_t)n * G4 + 4 * j);
        gi += gt.x; gf += gt.y; gg += gt.z; go += gt.w;
        c = sigf(gf) * g_c[idx] + sigf(gi) * tanhf(gg);
    }
    float h = sigf(go) * tanhf(c);
    g_c[idx] = c;
    __half hi = __float2half(h);
    g_hb_h[idx] = hi;
    g_hb_l[idx] = __float2half(h - __half2float(hi));
    g_compose[((size_t)n * TT + t) * DMODEL + dir * HH + j] = h;
}

// ---------------- K7: logits_rep (parallelized, deep ILP) ----------------
__global__ void logits_rep_kernel(const float* __restrict__ logits, const int* __restrict__ mask) {
    int b = blockIdx.x;
    int d = blockIdx.y * 128 + threadIdx.x;
    int tid = threadIdx.x;

    __shared__ unsigned char repl[SEQ];
    for (int i = tid; i < SEQ; i += blockDim.x) repl[i] = 0;
    __syncthreads();
    if (tid < 2 * HEADS) {
        int h = tid >> 1, half = tid & 1;
        int st = window_start(g_master[(b * HEADS + h) * 2 + half]);
        int base = half * LHALF + st;
        for (int k = 0; k < TT; k++) repl[base + k] = 1;
    }
    __syncthreads();
    for (int sPos = tid; sPos < SEQ; sPos += blockDim.x)
        repl[sPos] = (repl[sPos] && mask[b * SEQ + sPos] == 0) ? 1 : 0;
    __syncthreads();

    float a0 = 0.f, a1 = 0.f, a2 = 0.f, a3 = 0.f;
    const float* lp = logits + (size_t)b * SEQ * DMODEL + d;
    for (int sPos = 0; sPos < SEQ; sPos += 8) {
        float v0 = __ldg(lp + (size_t)(sPos + 0) * DMODEL);
        float v1 = __ldg(lp + (size_t)(sPos + 1) * DMODEL);
        float v2 = __ldg(lp + (size_t)(sPos + 2) * DMODEL);
        float v3 = __ldg(lp + (size_t)(sPos + 3) * DMODEL);
        float v4 = __ldg(lp + (size_t)(sPos + 4) * DMODEL);
        float v5 = __ldg(lp + (size_t)(sPos + 5) * DMODEL);
        float v6 = __ldg(lp + (size_t)(sPos + 6) * DMODEL);
        float v7 = __ldg(lp + (size_t)(sPos + 7) * DMODEL);
        a0 += repl[sPos]     ? EPSV : v0;
        a1 += repl[sPos + 1] ? EPSV : v1;
        a2 += repl[sPos + 2] ? EPSV : v2;
        a3 += repl[sPos + 3] ? EPSV : v3;
        a0 += repl[sPos + 4] ? EPSV : v4;
        a1 += repl[sPos + 5] ? EPSV : v5;
        a2 += repl[sPos + 6] ? EPSV : v6;
        a3 += repl[sPos + 7] ? EPSV : v7;
    }
    g_lrep[(size_t)b * DMODEL + d] = (a0 + a1 + a2 + a3) * (1.0f / (float)SEQ);
}

// ---------------- K8: final FC + softmax ----------------
__global__ void final_kernel(const float* __restrict__ fcw, const float* __restrict__ fcb,
                             float* __restrict__ out) {
    int b = blockIdx.x;
    int tid = threadIdx.x;
    const int NF = DMODEL * (HEADS + 1);
    float a0 = 0.0f, a1 = 0.0f;

    for (int j = tid; j < NF; j += 256) {
        float x;
        if (j < HEADS * DMODEL) {
            int h = j / DMODEL, d = j % DMODEL;
            int n = b * HEADS + h;
            const float* cp = g_compose + (size_t)n * TT * DMODEL + d;
            float s = 0.0f;
            #pragma unroll
            for (int t = 0; t < TT; t++) s += cp[(size_t)t * DMODEL];
            x = s * (1.0f / (float)TT);
        } else {
            x = g_lrep[(size_t)b * DMODEL + (j - HEADS * DMODEL)];
        }
        a0 += x * fcw[j];
        a1 += x * fcw[NF + j];
    }

    __shared__ float s0[256], s1[256];
    s0[tid] = a0; s1[tid] = a1;
    __syncthreads();
    for (int off = 128; off > 0; off >>= 1) {
        if (tid < off) { s0[tid] += s0[tid + off]; s1[tid] += s1[tid + off]; }
        __syncthreads();
    }
    if (tid == 0) {
        float l0 = s0[0] + fcb[0], l1 = s1[0] + fcb[1];
        float m = fmaxf(l0, l1);
        float e0 = expf(l0 - m), e1 = expf(l1 - m);
        float inv = 1.0f / (e0 + e1);
        out[b * 2 + 0] = e0 * inv;
        out[b * 2 + 1] = e1 * inv;
    }
}

// ---------------- launch ----------------
extern "C" void kernel_launch(void* const* d_in, const int* in_sizes, int n_in,
                              void* d_out, int out_size) {
    const int*   sents = (const int*)d_in[0];
    const float* att   = (const float*)d_in[1];
    const float* logits= (const float*)d_in[2];
    const int*   mask  = (const int*)d_in[3];
    const float* wih_f = (const float*)d_in[4];
    const float* whh_f = (const float*)d_in[5];
    const float* bih_f = (const float*)d_in[6];
    const float* bhh_f = (const float*)d_in[7];
    const float* wih_r = (const float*)d_in[8];
    const float* whh_r = (const float*)d_in[9];
    const float* bih_r = (const float*)d_in[10];
    const float* bhh_r = (const float*)d_in[11];
    const float* fc_w  = (const float*)d_in[12];
    const float* fc_b  = (const float*)d_in[13];
    float* out = (float*)d_out;

    cudaFuncSetAttribute(input_gemm_hmma, cudaFuncAttributeMaxDynamicSharedMemorySize, GM_SMEM);
    cudaFuncSetAttribute(rec_gemm_hmma, cudaFuncAttributeMaxDynamicSharedMemorySize, GM_SMEM);

    prep_kernel<<<(int)((PREP_TOTAL + 255) / 256), 256>>>(wih_f, wih_r, whh_f, whh_r,
                                                          bih_f, bhh_f, bih_r, bhh_r);
    masters_kernel<<<BH * 2, 256>>>(att, sents);
    build_slide<<<BH, 256>>>(logits, mask);

    // input GEMM: gatesX(2304x3072) = slide @ Wperm^T + bias
    input_gemm_hmma<<<dim3(2 * G4 / 128, BH * TT / 64), 256, GM_SMEM>>>();

    for (int s = 0; s < TT; s++) {
        lstm_point<<<(2 * BH * HH + 255) / 256, 256>>>(s);
        if (s < TT - 1) {
            rec_gemm_hmma<<<dim3(G4 / 128, BH / 64, 2), 256, GM_SMEM>>>();
        }
    }

    logits_rep_kernel<<<dim3(BATCH, DMODEL / 128), 128>>>(logits, mask);
    final_kernel<<<BATCH, 256>>>(fc_w, fc_b, out);
}

// round 14
// speedup vs baseline: 2.2959x; 1.1837x over previous
#include <cuda_runtime.h>
#include <cuda_fp16.h>
#include <math.h>
#include <stdint.h>

// ---------------- problem constants ----------------
#define BATCH  32
#define HEADS  12
#define SEQ    512
#define LHALF  256
#define DMODEL 768
#define HH     384          // hidden per direction
#define G4     1536         // 4*HH gates
#define DIN    1536         // 2*DMODEL LSTM input
#define BH     384          // BATCH*HEADS
#define TT     6            // SLIDER
#define EPSV   1e-9f

// ---------------- device scratch (no allocs allowed) ----------------
__device__ int   g_master[BH * 2];
__device__ float g_gatesX[(size_t)BH * TT * 2 * G4];   // 2304 x 3072, gate-interleaved cols (4*j+gate), bias folded
__device__ float g_gtmp[(size_t)2 * BH * G4];          // per-step h @ whh^T (gate-interleaved cols)
__device__ float g_c[(size_t)2 * BH * HH];
__device__ float g_compose[(size_t)BH * TT * DMODEL];
__device__ float g_lrep[(size_t)BATCH * DMODEL];

// fp16 operands (weights gate-interleaved rows: 4*j+gate)
__device__ __half g_slide[(size_t)BH * TT * DIN];
__device__ __half g_wih[(size_t)2 * G4 * DIN];
__device__ __half g_whh[(size_t)2 * G4 * HH];
__device__ __half g_hb[(size_t)2 * BH * HH];       // [dir][n][j]
__device__ float g_bias[2 * G4];                   // gate-interleaved

// ---------------- PTX helpers (baseline PTX only) ----------------
__device__ __forceinline__ uint32_t smem_u32(const void* p) {
    uint32_t a;
    asm("{ .reg .u64 t; cvta.to.shared.u64 t, %1; cvt.u32.u64 %0, t; }" : "=r"(a) : "l"(p));
    return a;
}

#define CP_ASYNC16(sm, gm) \
    asm volatile("cp.async.cg.shared.global [%0], [%1], 16;" :: "r"(sm), "l"(gm) : "memory")
#define CP_COMMIT() asm volatile("cp.async.commit_group;" ::: "memory")
#define CP_WAIT0()  asm volatile("cp.async.wait_group 0;" ::: "memory")

#define LDSM_X4(r0, r1, r2, r3, addr) \
    asm volatile("ldmatrix.sync.aligned.m8n8.x4.shared.b16 {%0,%1,%2,%3}, [%4];" \
        : "=r"(r0), "=r"(r1), "=r"(r2), "=r"(r3) : "r"(addr))

#define MMA_F16(c0, c1, c2, c3, a0, a1, a2, a3, b0, b1) \
    asm volatile("mma.sync.aligned.m16n8k16.row.col.f32.f16.f16.f32 " \
        "{%0,%1,%2,%3}, {%4,%5,%6,%7}, {%8,%9}, {%0,%1,%2,%3};" \
        : "+f"(c0), "+f"(c1), "+f"(c2), "+f"(c3) \
        : "r"(a0), "r"(a1), "r"(a2), "r"(a3), "r"(b0), "r"(b1))

// ---------------- helpers ----------------
__device__ __forceinline__ float sigf(float x) { return 1.0f / (1.0f + expf(-x)); }

__device__ __forceinline__ int window_start(int pos) {
    pos = min(max(pos, 1), LHALF - 2);
    int l = TT / 2;
    if (pos - TT / 2 <= 0) l = pos - 1;
    int r = TT - l;
    if (pos + r >= LHALF - 1) l = TT - (LHALF - pos - 2);
    return pos - l;
}

// ---------------- K1: masters (deep-MLP row sums) ----------------
__global__ void masters_kernel(const float* __restrict__ att, const int* __restrict__ sents) {
    int bid  = blockIdx.x;
    int half = bid & 1;
    int bh   = bid >> 1;
    int b    = bh / HEADS;

    __shared__ unsigned char seps[LHALF];
    __shared__ float rowsum[LHALF];

    int tid = threadIdx.x;
    {
        int j = half * LHALF + tid;
        seps[tid] = (sents[b * SEQ + j] == 102) ? 1 : 0;
    }
    __syncthreads();

    const float* base = att + ((size_t)bh * SEQ + (size_t)half * LHALF) * SEQ + (size_t)half * LHALF;

    int warp = tid >> 5, lane = tid & 31;
    #pragma unroll
    for (int rr = 0; rr < 32; rr += 4) {
        int row = warp * 32 + rr;
        const float4* r0 = (const float4*)(base + (size_t)(row + 0) * SEQ);
        const float4* r1 = (const float4*)(base + (size_t)(row + 1) * SEQ);
        const float4* r2 = (const float4*)(base + (size_t)(row + 2) * SEQ);
        const float4* r3 = (const float4*)(base + (size_t)(row + 3) * SEQ);
        float4 v0a = __ldg(r0 + lane), v0b = __ldg(r0 + lane + 32);
        float4 v1a = __ldg(r1 + lane), v1b = __ldg(r1 + lane + 32);
        float4 v2a = __ldg(r2 + lane), v2b = __ldg(r2 + lane + 32);
        float4 v3a = __ldg(r3 + lane), v3b = __ldg(r3 + lane + 32);

        int ja = lane * 4, jb = (lane + 32) * 4;
        float s0 = (seps[ja] ? EPSV : v0a.x) + (seps[ja+1] ? EPSV : v0a.y)
                 + (seps[ja+2] ? EPSV : v0a.z) + (seps[ja+3] ? EPSV : v0a.w)
                 + (seps[jb] ? EPSV : v0b.x) + (seps[jb+1] ? EPSV : v0b.y)
                 + (seps[jb+2] ? EPSV : v0b.z) + (seps[jb+3] ? EPSV : v0b.w);
        float s1 = (seps[ja] ? EPSV : v1a.x) + (seps[ja+1] ? EPSV : v1a.y)
                 + (seps[ja+2] ? EPSV : v1a.z) + (seps[ja+3] ? EPSV : v1a.w)
                 + (seps[jb] ? EPSV : v1b.x) + (seps[jb+1] ? EPSV : v1b.y)
                 + (seps[jb+2] ? EPSV : v1b.z) + (seps[jb+3] ? EPSV : v1b.w);
        float s2 = (seps[ja] ? EPSV : v2a.x) + (seps[ja+1] ? EPSV : v2a.y)
                 + (seps[ja+2] ? EPSV : v2a.z) + (seps[ja+3] ? EPSV : v2a.w)
                 + (seps[jb] ? EPSV : v2b.x) + (seps[jb+1] ? EPSV : v2b.y)
                 + (seps[jb+2] ? EPSV : v2b.z) + (seps[jb+3] ? EPSV : v2b.w);
        float s3 = (seps[ja] ? EPSV : v3a.x) + (seps[ja+1] ? EPSV : v3a.y)
                 + (seps[ja+2] ? EPSV : v3a.z) + (seps[ja+3] ? EPSV : v3a.w)
                 + (seps[jb] ? EPSV : v3b.x) + (seps[jb+1] ? EPSV : v3b.y)
                 + (seps[jb+2] ? EPSV : v3b.z) + (seps[jb+3] ? EPSV : v3b.w);

        #pragma unroll
        for (int off = 16; off > 0; off >>= 1) {
            s0 += __shfl_down_sync(0xffffffffu, s0, off);
            s1 += __shfl_down_sync(0xffffffffu, s1, off);
            s2 += __shfl_down_sync(0xffffffffu, s2, off);
            s3 += __shfl_down_sync(0xffffffffu, s3, off);
        }
        if (lane == 0) {
            rowsum[row]     = s0;
            rowsum[row + 1] = s1;
            rowsum[row + 2] = s2;
            rowsum[row + 3] = s3;
        }
    }
    __syncthreads();

    __shared__ float bv[LHALF];
    __shared__ int   bix[LHALF];
    bv[tid]  = rowsum[tid];
    bix[tid] = tid;
    __syncthreads();
    for (int off = 128; off > 0; off >>= 1) {
        if (tid < off) {
            float vo = bv[tid + off];
            int   io = bix[tid + off];
            if (vo > bv[tid] || (vo == bv[tid] && io < bix[tid])) { bv[tid] = vo; bix[tid] = io; }
        }
        __syncthreads();
    }
    if (tid == 0) g_master[bh * 2 + half] = bix[0];
}

// ---------------- K2: gather windows -> slide (fp16) ----------------
__global__ void build_slide(const float* __restrict__ logits, const int* __restrict__ mask) {
    int bh = blockIdx.x;
    int b  = bh / HEADS;
    __shared__ int sa, sb;
    if (threadIdx.x == 0) {
        sa = window_start(g_master[bh * 2 + 0]);
        sb = window_start(g_master[bh * 2 + 1]);
    }
    __syncthreads();

    for (int idx = threadIdx.x; idx < TT * DIN; idx += blockDim.x) {
        int t = idx / DIN, f = idx % DIN;
        float v;
        if (f < DMODEL) {
            int row = sa + t;
            v = (mask[b * SEQ + row] == 0) ? EPSV
                : logits[((size_t)b * SEQ + row) * DMODEL + f];
        } else {
            int row = LHALF + sb + t;
            v = (mask[b * SEQ + row] == 0) ? EPSV
                : logits[((size_t)b * SEQ + row) * DMODEL + (f - DMODEL)];
        }
        g_slide[(size_t)bh * (TT * DIN) + idx] = __float2half(v);
    }
}

// ---------------- K3: fused prep (fp16 weights with gate interleave + bias) ----------------
#define NW ((size_t)G4 * DIN)    // 2359296
#define NH ((size_t)G4 * HH)     // 589824
#define PREP_TOTAL (2 * NW + 2 * NH + 2 * G4)

__global__ void prep_kernel(const float* __restrict__ wih_f, const float* __restrict__ wih_r,
                            const float* __restrict__ whh_f, const float* __restrict__ whh_r,
                            const float* __restrict__ bihf, const float* __restrict__ bhhf,
                            const float* __restrict__ bihr, const float* __restrict__ bhhr) {
    size_t i = (size_t)blockIdx.x * blockDim.x + threadIdx.x;
    if (i >= PREP_TOTAL) return;
    if (i < 2 * NW + 2 * NH) {
        const float* src;
        __half* dh;
        size_t off;
        int kdim;
        if (i < NW)               { src = wih_f; dh = g_wih;      off = i;                kdim = DIN; }
        else if (i < 2 * NW)      { src = wih_r; dh = g_wih + NW; off = i - NW;           kdim = DIN; }
        else if (i < 2 * NW + NH) { src = whh_f; dh = g_whh;      off = i - 2 * NW;       kdim = HH;  }
        else                      { src = whh_r; dh = g_whh + NH; off = i - 2 * NW - NH;  kdim = HH;  }
        size_t row = off / kdim, k = off % kdim;
        int gate = (int)(row / HH), j = (int)(row % HH);
        size_t drow = (size_t)(4 * j + gate);
        dh[drow * kdim + k] = __float2half(src[off]);
    } else {
        size_t q = i - (2 * NW + 2 * NH);      // [0, 2*G4)
        int dir = (int)(q / G4);
        int r   = (int)(q % G4);
        int gate = r / HH, j = r % HH;
        float v = dir ? (bihr[r] + bhhr[r]) : (bihf[r] + bhhf[r]);
        g_bias[dir * G4 + 4 * j + gate] = v;
    }
}

// ---------------- GEMM core: tile 64(M) x 128(N), fp16 single product, 2 CTAs/SM ----------------
// Chunk layout: A(8KB) | B(16KB) = 24KB, double buffered.
#define BK          64
#define A_CHUNK     8192           // 64 rows x 128B
#define B_CHUNK     16384          // 128 rows x 128B
#define BUF_BYTES   (A_CHUNK + B_CHUNK)       // 24576
#define GM_SMEM     (1024 + 2 * BUF_BYTES)    // 50176

__device__ __forceinline__ void gemm_core(
    const __half* A, const __half* B,
    int bm, int bn, int K, int NC,
    char* smem_raw, uint32_t tiles_u,
    int tid, int lane, int wm, int wn,
    float acc[2][4][4])
{
    int Kd8 = K >> 3;

    auto load_chunk = [&](int c, int buf) {
        int k0 = c * BK;
        uint32_t bufu = tiles_u + buf * BUF_BYTES;
        // A operand: 64 rows, 512 uint4 -> 2 per thread
        {
            const uint4* gp = (const uint4*)(A + (size_t)bm * K + k0);
            #pragma unroll
            for (int i = 0; i < 2; i++) {
                int u = tid + i * 256;
                int r = u >> 3, c16 = u & 7;
                const uint4* ga = gp + (size_t)r * Kd8 + c16;
                uint32_t off = (uint32_t)(r * 128 + c16 * 16);
                uint32_t sw = off ^ ((off >> 3) & 0x70);
                CP_ASYNC16(bufu + sw, ga);
            }
        }
        // B operand: 128 rows, 1024 uint4 -> 4 per thread
        {
            const uint4* gp = (const uint4*)(B + (size_t)bn * K + k0);
            uint32_t tb = bufu + A_CHUNK;
            #pragma unroll
            for (int i = 0; i < 4; i++) {
                int u = tid + i * 256;
                int r = u >> 3, c16 = u & 7;
                const uint4* ga = gp + (size_t)r * Kd8 + c16;
                uint32_t off = (uint32_t)(r * 128 + c16 * 16);
                uint32_t sw = off ^ ((off >> 3) & 0x70);
                CP_ASYNC16(tb + sw, ga);
            }
        }
    };

    load_chunk(0, 0);
    CP_COMMIT();

    for (int c = 0; c < NC; c++) {
        CP_WAIT0();
        __syncthreads();
        if (c + 1 < NC) { load_chunk(c + 1, (c + 1) & 1); CP_COMMIT(); }

        uint32_t base = tiles_u + (c & 1) * BUF_BYTES;
        uint32_t a_base = base;
        uint32_t b_base = base + A_CHUNK;

        #pragma unroll
        for (int ks = 0; ks < 4; ks++) {
            uint32_t a[2][4];
            #pragma unroll
            for (int mt = 0; mt < 2; mt++) {
                uint32_t r = wm + mt * 16 + (lane & 15);
                uint32_t coloff = ks * 32 + ((lane >> 4) & 1) * 16;
                uint32_t off = r * 128 + coloff;
                uint32_t sw = off ^ ((off >> 3) & 0x70);
                LDSM_X4(a[mt][0], a[mt][1], a[mt][2], a[mt][3], a_base + sw);
            }
            uint32_t b[4][2];
            #pragma unroll
            for (int h = 0; h < 2; h++) {
                uint32_t r = wn + h * 16 + (lane & 7) + ((lane >> 4) << 3);
                uint32_t coloff = ks * 32 + ((lane >> 3) & 1) * 16;
                uint32_t off = r * 128 + coloff;
                uint32_t sw = off ^ ((off >> 3) & 0x70);
                uint32_t r0, r1, r2, r3;
                LDSM_X4(r0, r1, r2, r3, b_base + sw);
                b[2 * h][0] = r0; b[2 * h][1] = r1;
                b[2 * h + 1][0] = r2; b[2 * h + 1][1] = r3;
            }
            #pragma unroll
            for (int mt = 0; mt < 2; mt++)
                #pragma unroll
                for (int nt = 0; nt < 4; nt++)
                    MMA_F16(acc[mt][nt][0], acc[mt][nt][1], acc[mt][nt][2], acc[mt][nt][3],
                            a[mt][0], a[mt][1], a[mt][2], a[mt][3],
                            b[nt][0], b[nt][1]);
        }
        __syncthreads();
    }
}

// ---------------- K4: input GEMM (tile 64x128, 2 CTAs/SM) ----------------
__global__ __launch_bounds__(256, 2) void input_gemm_hmma() {
    extern __shared__ char smem_raw[];
    uint32_t smem_u = smem_u32(smem_raw);
    uint32_t tiles_u = (smem_u + 1023) & ~1023u;

    int tid = threadIdx.x, wid = tid >> 5, lane = tid & 31;
    int wm = (wid & 1) * 32, wn = (wid >> 1) * 32;
    int bm = blockIdx.y * 64;
    int bn = blockIdx.x * 128;

    float acc[2][4][4];
    #pragma unroll
    for (int i = 0; i < 2; i++)
        #pragma unroll
        for (int j = 0; j < 4; j++)
            #pragma unroll
            for (int q = 0; q < 4; q++) acc[i][j][q] = 0.0f;

    gemm_core(g_slide, g_wih, bm, bn, DIN, DIN / BK,
              smem_raw, tiles_u, tid, lane, wm, wn, acc);

    #pragma unroll
    for (int mt = 0; mt < 2; mt++) {
        #pragma unroll
        for (int nt = 0; nt < 4; nt++) {
            int row = bm + wm + mt * 16 + (lane >> 2);
            int col = bn + wn + nt * 8 + (lane & 3) * 2;
            float b0 = g_bias[col], b1 = g_bias[col + 1];
            float2 v0 = make_float2(acc[mt][nt][0] + b0, acc[mt][nt][1] + b1);
            float2 v1 = make_float2(acc[mt][nt][2] + b0, acc[mt][nt][3] + b1);
            *(float2*)(g_gatesX + (size_t)row * (2 * G4) + col) = v0;
            *(float2*)(g_gatesX + (size_t)(row + 8) * (2 * G4) + col) = v1;
        }
    }
}

// ---------------- K5: recurrent GEMM  gtmp[dir] = h[dir] @ whh[dir]^T ----------------
__global__ __launch_bounds__(256, 2) void rec_gemm_hmma() {
    extern __shared__ char smem_raw[];
    uint32_t smem_u = smem_u32(smem_raw);
    uint32_t tiles_u = (smem_u + 1023) & ~1023u;

    int z = blockIdx.z;
    const __half* A = g_hb + (size_t)z * BH * HH;
    const __half* B = g_whh + (size_t)z * G4 * HH;
    float* C = g_gtmp + (size_t)z * BH * G4;

    int tid = threadIdx.x, wid = tid >> 5, lane = tid & 31;
    int wm = (wid & 1) * 32, wn = (wid >> 1) * 32;
    int bm = blockIdx.y * 64;
    int bn = blockIdx.x * 128;

    float acc[2][4][4];
    #pragma unroll
    for (int i = 0; i < 2; i++)
        #pragma unroll
        for (int j = 0; j < 4; j++)
            #pragma unroll
            for (int q = 0; q < 4; q++) acc[i][j][q] = 0.0f;

    gemm_core(A, B, bm, bn, HH, HH / BK,
              smem_raw, tiles_u, tid, lane, wm, wn, acc);

    #pragma unroll
    for (int mt = 0; mt < 2; mt++) {
        #pragma unroll
        for (int nt = 0; nt < 4; nt++) {
            int row = bm + wm + mt * 16 + (lane >> 2);
            int col = bn + wn + nt * 8 + (lane & 3) * 2;
            float2 v0 = make_float2(acc[mt][nt][0], acc[mt][nt][1]);
            float2 v1 = make_float2(acc[mt][nt][2], acc[mt][nt][3]);
            *(float2*)(C + (size_t)row * G4 + col) = v0;
            *(float2*)(C + (size_t)(row + 8) * G4 + col) = v1;
        }
    }
}

// ---------------- K6: per-step LSTM pointwise (gate-interleaved float4 reads) ----------------
__global__ void lstm_point(int s) {
    int idx = blockIdx.x * blockDim.x + threadIdx.x;
    if (idx >= 2 * BH * HH) return;
    int dir = idx / (BH * HH);
    int r   = idx % (BH * HH);
    int n   = r / HH;
    int j   = r % HH;
    int t   = dir ? (TT - 1 - s) : s;

    float4 gx = *(const float4*)(g_gatesX + ((size_t)(n * TT + t)) * (2 * G4)
                                 + (size_t)dir * G4 + 4 * j);
    float gi = gx.x, gf = gx.y, gg = gx.z, go = gx.w;

    float c;
    if (s == 0) {
        c = sigf(gi) * tanhf(gg);
    } else {
        float4 gt = *(const float4*)(g_gtmp + (size_t)dir * BH * G4 + (size_t)n * G4 + 4 * j);
        gi += gt.x; gf += gt.y; gg += gt.z; go += gt.w;
        c = sigf(gf) * g_c[idx] + sigf(gi) * tanhf(gg);
    }
    float h = sigf(go) * tanhf(c);
    g_c[idx] = c;
    g_hb[idx] = __float2half(h);
    g_compose[((size_t)n * TT + t) * DMODEL + dir * HH + j] = h;
}

// ---------------- K7: logits_rep (parallelized, deep ILP) ----------------
__global__ void logits_rep_kernel(const float* __restrict__ logits, const int* __restrict__ mask) {
    int b = blockIdx.x;
    int d = blockIdx.y * 128 + threadIdx.x;
    int tid = threadIdx.x;

    __shared__ unsigned char repl[SEQ];
    for (int i = tid; i < SEQ; i += blockDim.x) repl[i] = 0;
    __syncthreads();
    if (tid < 2 * HEADS) {
        int h = tid >> 1, half = tid & 1;
        int st = window_start(g_master[(b * HEADS + h) * 2 + half]);
        int base = half * LHALF + st;
        for (int k = 0; k < TT; k++) repl[base + k] = 1;
    }
    __syncthreads();
    for (int sPos = tid; sPos < SEQ; sPos += blockDim.x)
        repl[sPos] = (repl[sPos] && mask[b * SEQ + sPos] == 0) ? 1 : 0;
    __syncthreads();

    float a0 = 0.f, a1 = 0.f, a2 = 0.f, a3 = 0.f;
    const float* lp = logits + (size_t)b * SEQ * DMODEL + d;
    for (int sPos = 0; sPos < SEQ; sPos += 8) {
        float v0 = __ldg(lp + (size_t)(sPos + 0) * DMODEL);
        float v1 = __ldg(lp + (size_t)(sPos + 1) * DMODEL);
        float v2 = __ldg(lp + (size_t)(sPos + 2) * DMODEL);
        float v3 = __ldg(lp + (size_t)(sPos + 3) * DMODEL);
        float v4 = __ldg(lp + (size_t)(sPos + 4) * DMODEL);
        float v5 = __ldg(lp + (size_t)(sPos + 5) * DMODEL);
        float v6 = __ldg(lp + (size_t)(sPos + 6) * DMODEL);
        float v7 = __ldg(lp + (size_t)(sPos + 7) * DMODEL);
        a0 += repl[sPos]     ? EPSV : v0;
        a1 += repl[sPos + 1] ? EPSV : v1;
        a2 += repl[sPos + 2] ? EPSV : v2;
        a3 += repl[sPos + 3] ? EPSV : v3;
        a0 += repl[sPos + 4] ? EPSV : v4;
        a1 += repl[sPos + 5] ? EPSV : v5;
        a2 += repl[sPos + 6] ? EPSV : v6;
        a3 += repl[sPos + 7] ? EPSV : v7;
    }
    g_lrep[(size_t)b * DMODEL + d] = (a0 + a1 + a2 + a3) * (1.0f / (float)SEQ);
}

// ---------------- K8: final FC + softmax ----------------
__global__ void final_kernel(const float* __restrict__ fcw, const float* __restrict__ fcb,
                             float* __restrict__ out) {
    int b = blockIdx.x;
    int tid = threadIdx.x;
    const int NF = DMODEL * (HEADS + 1);
    float a0 = 0.0f, a1 = 0.0f;

    for (int j = tid; j < NF; j += 256) {
        float x;
        if (j < HEADS * DMODEL) {
            int h = j / DMODEL, d = j % DMODEL;
            int n = b * HEADS + h;
            const float* cp = g_compose + (size_t)n * TT * DMODEL + d;
            float s = 0.0f;
            #pragma unroll
            for (int t = 0; t < TT; t++) s += cp[(size_t)t * DMODEL];
            x = s * (1.0f / (float)TT);
        } else {
            x = g_lrep[(size_t)b * DMODEL + (j - HEADS * DMODEL)];
        }
        a0 += x * fcw[j];
        a1 += x * fcw[NF + j];
    }

    __shared__ float s0[256], s1[256];
    s0[tid] = a0; s1[tid] = a1;
    __syncthreads();
    for (int off = 128; off > 0; off >>= 1) {
        if (tid < off) { s0[tid] += s0[tid + off]; s1[tid] += s1[tid + off]; }
        __syncthreads();
    }
    if (tid == 0) {
        float l0 = s0[0] + fcb[0], l1 = s1[0] + fcb[1];
        float m = fmaxf(l0, l1);
        float e0 = expf(l0 - m), e1 = expf(l1 - m);
        float inv = 1.0f / (e0 + e1);
        out[b * 2 + 0] = e0 * inv;
        out[b * 2 + 1] = e1 * inv;
    }
}

// ---------------- launch ----------------
extern "C" void kernel_launch(void* const* d_in, const int* in_sizes, int n_in,
                              void* d_out, int out_size) {
    const int*   sents = (const int*)d_in[0];
    const float* att   = (const float*)d_in[1];
    const float* logits= (const float*)d_in[2];
    const int*   mask  = (const int*)d_in[3];
    const float* wih_f = (const float*)d_in[4];
    const float* whh_f = (const float*)d_in[5];
    const float* bih_f = (const float*)d_in[6];
    const float* bhh_f = (const float*)d_in[7];
    const float* wih_r = (const float*)d_in[8];
    const float* whh_r = (const float*)d_in[9];
    const float* bih_r = (const float*)d_in[10];
    const float* bhh_r = (const float*)d_in[11];
    const float* fc_w  = (const float*)d_in[12];
    const float* fc_b  = (const float*)d_in[13];
    float* out = (float*)d_out;

    cudaFuncSetAttribute(input_gemm_hmma, cudaFuncAttributeMaxDynamicSharedMemorySize, GM_SMEM);
    cudaFuncSetAttribute(rec_gemm_hmma, cudaFuncAttributeMaxDynamicSharedMemorySize, GM_SMEM);

    prep_kernel<<<(int)((PREP_TOTAL + 255) / 256), 256>>>(wih_f, wih_r, whh_f, whh_r,
                                                          bih_f, bhh_f, bih_r, bhh_r);
    masters_kernel<<<BH * 2, 256>>>(att, sents);
    build_slide<<<BH, 256>>>(logits, mask);

    // input GEMM: gatesX(2304x3072) = slide @ Wperm^T + bias
    input_gemm_hmma<<<dim3(2 * G4 / 128, BH * TT / 64), 256, GM_SMEM>>>();

    for (int s = 0; s < TT; s++) {
        lstm_point<<<(2 * BH * HH + 255) / 256, 256>>>(s);
        if (s < TT - 1) {
            rec_gemm_hmma<<<dim3(G4 / 128, BH / 64, 2), 256, GM_SMEM>>>();
        }
    }

    logits_rep_kernel<<<dim3(BATCH, DMODEL / 128), 128>>>(logits, mask);
    final_kernel<<<BATCH, 256>>>(fc_w, fc_b, out);
}

// round 15
// speedup vs baseline: 2.3648x; 1.0300x over previous
#include <cuda_runtime.h>
#include <cuda_fp16.h>
#include <math.h>
#include <stdint.h>

// ---------------- problem constants ----------------
#define BATCH  32
#define HEADS  12
#define SEQ    512
#define LHALF  256
#define DMODEL 768
#define HH     384          // hidden per direction
#define G4     1536         // 4*HH gates
#define DIN    1536         // 2*DMODEL LSTM input
#define BH     384          // BATCH*HEADS
#define TT     6            // SLIDER
#define EPSV   1e-9f

// ---------------- device scratch (no allocs allowed) ----------------
__device__ int    g_master[BH * 2];
__device__ __half g_gatesX[(size_t)BH * TT * 2 * G4];   // fp16, gate-interleaved cols (4*j+gate), bias folded
__device__ __half g_gtmp[(size_t)2 * BH * G4];          // fp16, per-step h @ whh^T
__device__ float  g_c[(size_t)2 * BH * HH];
__device__ float  g_compose[(size_t)BH * TT * DMODEL];
__device__ float  g_lrep[(size_t)BATCH * DMODEL];

// fp16 operands (weights gate-interleaved rows: 4*j+gate)
__device__ __half g_slide[(size_t)BH * TT * DIN];
__device__ __half g_wih[(size_t)2 * G4 * DIN];
__device__ __half g_whh[(size_t)2 * G4 * HH];
__device__ __half g_hb[(size_t)2 * BH * HH];       // [dir][n][j]
__device__ float  g_bias[2 * G4];                  // gate-interleaved

// ---------------- PTX helpers (baseline PTX only) ----------------
__device__ __forceinline__ uint32_t smem_u32(const void* p) {
    uint32_t a;
    asm("{ .reg .u64 t; cvta.to.shared.u64 t, %1; cvt.u32.u64 %0, t; }" : "=r"(a) : "l"(p));
    return a;
}

#define CP_ASYNC16(sm, gm) \
    asm volatile("cp.async.cg.shared.global [%0], [%1], 16;" :: "r"(sm), "l"(gm) : "memory")
#define CP_COMMIT() asm volatile("cp.async.commit_group;" ::: "memory")
#define CP_WAIT0()  asm volatile("cp.async.wait_group 0;" ::: "memory")

#define LDSM_X4(r0, r1, r2, r3, addr) \
    asm volatile("ldmatrix.sync.aligned.m8n8.x4.shared.b16 {%0,%1,%2,%3}, [%4];" \
        : "=r"(r0), "=r"(r1), "=r"(r2), "=r"(r3) : "r"(addr))

#define MMA_F16(c0, c1, c2, c3, a0, a1, a2, a3, b0, b1) \
    asm volatile("mma.sync.aligned.m16n8k16.row.col.f32.f16.f16.f32 " \
        "{%0,%1,%2,%3}, {%4,%5,%6,%7}, {%8,%9}, {%0,%1,%2,%3};" \
        : "+f"(c0), "+f"(c1), "+f"(c2), "+f"(c3) \
        : "r"(a0), "r"(a1), "r"(a2), "r"(a3), "r"(b0), "r"(b1))

// ---------------- helpers ----------------
__device__ __forceinline__ float sigf(float x) { return 1.0f / (1.0f + expf(-x)); }

__device__ __forceinline__ int window_start(int pos) {
    pos = min(max(pos, 1), LHALF - 2);
    int l = TT / 2;
    if (pos - TT / 2 <= 0) l = pos - 1;
    int r = TT - l;
    if (pos + r >= LHALF - 1) l = TT - (LHALF - pos - 2);
    return pos - l;
}

// ---------------- K1: masters (deep-MLP row sums) ----------------
__global__ void masters_kernel(const float* __restrict__ att, const int* __restrict__ sents) {
    int bid  = blockIdx.x;
    int half = bid & 1;
    int bh   = bid >> 1;
    int b    = bh / HEADS;

    __shared__ unsigned char seps[LHALF];
    __shared__ float rowsum[LHALF];

    int tid = threadIdx.x;
    {
        int j = half * LHALF + tid;
        seps[tid] = (sents[b * SEQ + j] == 102) ? 1 : 0;
    }
    __syncthreads();

    const float* base = att + ((size_t)bh * SEQ + (size_t)half * LHALF) * SEQ + (size_t)half * LHALF;

    int warp = tid >> 5, lane = tid & 31;
    #pragma unroll
    for (int rr = 0; rr < 32; rr += 4) {
        int row = warp * 32 + rr;
        const float4* r0 = (const float4*)(base + (size_t)(row + 0) * SEQ);
        const float4* r1 = (const float4*)(base + (size_t)(row + 1) * SEQ);
        const float4* r2 = (const float4*)(base + (size_t)(row + 2) * SEQ);
        const float4* r3 = (const float4*)(base + (size_t)(row + 3) * SEQ);
        float4 v0a = __ldg(r0 + lane), v0b = __ldg(r0 + lane + 32);
        float4 v1a = __ldg(r1 + lane), v1b = __ldg(r1 + lane + 32);
        float4 v2a = __ldg(r2 + lane), v2b = __ldg(r2 + lane + 32);
        float4 v3a = __ldg(r3 + lane), v3b = __ldg(r3 + lane + 32);

        int ja = lane * 4, jb = (lane + 32) * 4;
        float s0 = (seps[ja] ? EPSV : v0a.x) + (seps[ja+1] ? EPSV : v0a.y)
                 + (seps[ja+2] ? EPSV : v0a.z) + (seps[ja+3] ? EPSV : v0a.w)
                 + (seps[jb] ? EPSV : v0b.x) + (seps[jb+1] ? EPSV : v0b.y)
                 + (seps[jb+2] ? EPSV : v0b.z) + (seps[jb+3] ? EPSV : v0b.w);
        float s1 = (seps[ja] ? EPSV : v1a.x) + (seps[ja+1] ? EPSV : v1a.y)
                 + (seps[ja+2] ? EPSV : v1a.z) + (seps[ja+3] ? EPSV : v1a.w)
                 + (seps[jb] ? EPSV : v1b.x) + (seps[jb+1] ? EPSV : v1b.y)
                 + (seps[jb+2] ? EPSV : v1b.z) + (seps[jb+3] ? EPSV : v1b.w);
        float s2 = (seps[ja] ? EPSV : v2a.x) + (seps[ja+1] ? EPSV : v2a.y)
                 + (seps[ja+2] ? EPSV : v2a.z) + (seps[ja+3] ? EPSV : v2a.w)
                 + (seps[jb] ? EPSV : v2b.x) + (seps[jb+1] ? EPSV : v2b.y)
                 + (seps[jb+2] ? EPSV : v2b.z) + (seps[jb+3] ? EPSV : v2b.w);
        float s3 = (seps[ja] ? EPSV : v3a.x) + (seps[ja+1] ? EPSV : v3a.y)
                 + (seps[ja+2] ? EPSV : v3a.z) + (seps[ja+3] ? EPSV : v3a.w)
                 + (seps[jb] ? EPSV : v3b.x) + (seps[jb+1] ? EPSV : v3b.y)
                 + (seps[jb+2] ? EPSV : v3b.z) + (seps[jb+3] ? EPSV : v3b.w);

        #pragma unroll
        for (int off = 16; off > 0; off >>= 1) {
            s0 += __shfl_down_sync(0xffffffffu, s0, off);
            s1 += __shfl_down_sync(0xffffffffu, s1, off);
            s2 += __shfl_down_sync(0xffffffffu, s2, off);
            s3 += __shfl_down_sync(0xffffffffu, s3, off);
        }
        if (lane == 0) {
            rowsum[row]     = s0;
            rowsum[row + 1] = s1;
            rowsum[row + 2] = s2;
            rowsum[row + 3] = s3;
        }
    }
    __syncthreads();

    __shared__ float bv[LHALF];
    __shared__ int   bix[LHALF];
    bv[tid]  = rowsum[tid];
    bix[tid] = tid;
    __syncthreads();
    for (int off = 128; off > 0; off >>= 1) {
        if (tid < off) {
            float vo = bv[tid + off];
            int   io = bix[tid + off];
            if (vo > bv[tid] || (vo == bv[tid] && io < bix[tid])) { bv[tid] = vo; bix[tid] = io; }
        }
        __syncthreads();
    }
    if (tid == 0) g_master[bh * 2 + half] = bix[0];
}

// ---------------- K2: gather windows -> slide (fp16) ----------------
__global__ void build_slide(const float* __restrict__ logits, const int* __restrict__ mask) {
    int bh = blockIdx.x;
    int b  = bh / HEADS;
    __shared__ int sa, sb;
    if (threadIdx.x == 0) {
        sa = window_start(g_master[bh * 2 + 0]);
        sb = window_start(g_master[bh * 2 + 1]);
    }
    __syncthreads();

    for (int idx = threadIdx.x; idx < TT * DIN; idx += blockDim.x) {
        int t = idx / DIN, f = idx % DIN;
        float v;
        if (f < DMODEL) {
            int row = sa + t;
            v = (mask[b * SEQ + row] == 0) ? EPSV
                : logits[((size_t)b * SEQ + row) * DMODEL + f];
        } else {
            int row = LHALF + sb + t;
            v = (mask[b * SEQ + row] == 0) ? EPSV
                : logits[((size_t)b * SEQ + row) * DMODEL + (f - DMODEL)];
        }
        g_slide[(size_t)bh * (TT * DIN) + idx] = __float2half(v);
    }
}

// ---------------- K3: fused prep (fp16 weights with gate interleave + bias) ----------------
#define NW ((size_t)G4 * DIN)    // 2359296
#define NH ((size_t)G4 * HH)     // 589824
#define PREP_TOTAL (2 * NW + 2 * NH + 2 * G4)

__global__ void prep_kernel(const float* __restrict__ wih_f, const float* __restrict__ wih_r,
                            const float* __restrict__ whh_f, const float* __restrict__ whh_r,
                            const float* __restrict__ bihf, const float* __restrict__ bhhf,
                            const float* __restrict__ bihr, const float* __restrict__ bhhr) {
    size_t i = (size_t)blockIdx.x * blockDim.x + threadIdx.x;
    if (i >= PREP_TOTAL) return;
    if (i < 2 * NW + 2 * NH) {
        const float* src;
        __half* dh;
        size_t off;
        int kdim;
        if (i < NW)               { src = wih_f; dh = g_wih;      off = i;                kdim = DIN; }
        else if (i < 2 * NW)      { src = wih_r; dh = g_wih + NW; off = i - NW;           kdim = DIN; }
        else if (i < 2 * NW + NH) { src = whh_f; dh = g_whh;      off = i - 2 * NW;       kdim = HH;  }
        else                      { src = whh_r; dh = g_whh + NH; off = i - 2 * NW - NH;  kdim = HH;  }
        size_t row = off / kdim, k = off % kdim;
        int gate = (int)(row / HH), j = (int)(row % HH);
        size_t drow = (size_t)(4 * j + gate);
        dh[drow * kdim + k] = __float2half(src[off]);
    } else {
        size_t q = i - (2 * NW + 2 * NH);      // [0, 2*G4)
        int dir = (int)(q / G4);
        int r   = (int)(q % G4);
        int gate = r / HH, j = r % HH;
        float v = dir ? (bihr[r] + bhhr[r]) : (bihf[r] + bhhf[r]);
        g_bias[dir * G4 + 4 * j + gate] = v;
    }
}

// ---------------- GEMM core: tile 64(M) x 192(N), fp16 single product, 2 CTAs/SM ----------------
// Chunk layout: A(8KB) | B(24KB) = 32KB, double buffered.
#define BK          64
#define BN          192
#define A_CHUNK     8192           // 64 rows x 128B
#define B_CHUNK     24576          // 192 rows x 128B
#define BUF_BYTES   (A_CHUNK + B_CHUNK)       // 32768
#define GM_SMEM     (1024 + 2 * BUF_BYTES)    // 66560

__device__ __forceinline__ void gemm_core(
    const __half* A, const __half* B,
    int bm, int bn, int K, int NC,
    char* smem_raw, uint32_t tiles_u,
    int tid, int lane, int wm, int wn,
    float acc[2][6][4])
{
    int Kd8 = K >> 3;

    auto load_chunk = [&](int c, int buf) {
        int k0 = c * BK;
        uint32_t bufu = tiles_u + buf * BUF_BYTES;
        // A operand: 64 rows, 512 uint4 -> 2 per thread
        {
            const uint4* gp = (const uint4*)(A + (size_t)bm * K + k0);
            #pragma unroll
            for (int i = 0; i < 2; i++) {
                int u = tid + i * 256;
                int r = u >> 3, c16 = u & 7;
                const uint4* ga = gp + (size_t)r * Kd8 + c16;
                uint32_t off = (uint32_t)(r * 128 + c16 * 16);
                uint32_t sw = off ^ ((off >> 3) & 0x70);
                CP_ASYNC16(bufu + sw, ga);
            }
        }
        // B operand: 192 rows, 1536 uint4 -> 6 per thread
        {
            const uint4* gp = (const uint4*)(B + (size_t)bn * K + k0);
            uint32_t tb = bufu + A_CHUNK;
            #pragma unroll
            for (int i = 0; i < 6; i++) {
                int u = tid + i * 256;
                int r = u >> 3, c16 = u & 7;
                const uint4* ga = gp + (size_t)r * Kd8 + c16;
                uint32_t off = (uint32_t)(r * 128 + c16 * 16);
                uint32_t sw = off ^ ((off >> 3) & 0x70);
                CP_ASYNC16(tb + sw, ga);
            }
        }
    };

    load_chunk(0, 0);
    CP_COMMIT();

    for (int c = 0; c < NC; c++) {
        CP_WAIT0();
        __syncthreads();
        if (c + 1 < NC) { load_chunk(c + 1, (c + 1) & 1); CP_COMMIT(); }

        uint32_t base = tiles_u + (c & 1) * BUF_BYTES;
        uint32_t a_base = base;
        uint32_t b_base = base + A_CHUNK;

        #pragma unroll
        for (int ks = 0; ks < 4; ks++) {
            uint32_t a[2][4];
            #pragma unroll
            for (int mt = 0; mt < 2; mt++) {
                uint32_t r = wm + mt * 16 + (lane & 15);
                uint32_t coloff = ks * 32 + ((lane >> 4) & 1) * 16;
                uint32_t off = r * 128 + coloff;
                uint32_t sw = off ^ ((off >> 3) & 0x70);
                LDSM_X4(a[mt][0], a[mt][1], a[mt][2], a[mt][3], a_base + sw);
            }
            uint32_t b[6][2];
            #pragma unroll
            for (int h = 0; h < 3; h++) {
                uint32_t r = wn + h * 16 + (lane & 7) + ((lane >> 4) << 3);
                uint32_t coloff = ks * 32 + ((lane >> 3) & 1) * 16;
                uint32_t off = r * 128 + coloff;
                uint32_t sw = off ^ ((off >> 3) & 0x70);
                uint32_t r0, r1, r2, r3;
                LDSM_X4(r0, r1, r2, r3, b_base + sw);
                b[2 * h][0] = r0; b[2 * h][1] = r1;
                b[2 * h + 1][0] = r2; b[2 * h + 1][1] = r3;
            }
            #pragma unroll
            for (int mt = 0; mt < 2; mt++)
                #pragma unroll
                for (int nt = 0; nt < 6; nt++)
                    MMA_F16(acc[mt][nt][0], acc[mt][nt][1], acc[mt][nt][2], acc[mt][nt][3],
                            a[mt][0], a[mt][1], a[mt][2], a[mt][3],
                            b[nt][0], b[nt][1]);
        }
        __syncthreads();
    }
}

// ---------------- K4: input GEMM (tile 64x192, 2 CTAs/SM) ----------------
__global__ __launch_bounds__(256, 2) void input_gemm_hmma() {
    extern __shared__ char smem_raw[];
    uint32_t smem_u = smem_u32(smem_raw);
    uint32_t tiles_u = (smem_u + 1023) & ~1023u;

    int tid = threadIdx.x, wid = tid >> 5, lane = tid & 31;
    int wm = (wid & 1) * 32, wn = (wid >> 1) * 48;
    int bm = blockIdx.y * 64;
    int bn = blockIdx.x * BN;

    float acc[2][6][4];
    #pragma unroll
    for (int i = 0; i < 2; i++)
        #pragma unroll
        for (int j = 0; j < 6; j++)
            #pragma unroll
            for (int q = 0; q < 4; q++) acc[i][j][q] = 0.0f;

    gemm_core(g_slide, g_wih, bm, bn, DIN, DIN / BK,
              smem_raw, tiles_u, tid, lane, wm, wn, acc);

    #pragma unroll
    for (int mt = 0; mt < 2; mt++) {
        #pragma unroll
        for (int nt = 0; nt < 6; nt++) {
            int row = bm + wm + mt * 16 + (lane >> 2);
            int col = bn + wn + nt * 8 + (lane & 3) * 2;
            float b0 = g_bias[col], b1 = g_bias[col + 1];
            __half2 v0 = __floats2half2_rn(acc[mt][nt][0] + b0, acc[mt][nt][1] + b1);
            __half2 v1 = __floats2half2_rn(acc[mt][nt][2] + b0, acc[mt][nt][3] + b1);
            *(__half2*)(g_gatesX + (size_t)row * (2 * G4) + col) = v0;
            *(__half2*)(g_gatesX + (size_t)(row + 8) * (2 * G4) + col) = v1;
        }
    }
}

// ---------------- K5: recurrent GEMM  gtmp[dir] = h[dir] @ whh[dir]^T ----------------
__global__ __launch_bounds__(256, 2) void rec_gemm_hmma() {
    extern __shared__ char smem_raw[];
    uint32_t smem_u = smem_u32(smem_raw);
    uint32_t tiles_u = (smem_u + 1023) & ~1023u;

    int z = blockIdx.z;
    const __half* A = g_hb + (size_t)z * BH * HH;
    const __half* B = g_whh + (size_t)z * G4 * HH;
    __half* C = g_gtmp + (size_t)z * BH * G4;

    int tid = threadIdx.x, wid = tid >> 5, lane = tid & 31;
    int wm = (wid & 1) * 32, wn = (wid >> 1) * 48;
    int bm = blockIdx.y * 64;
    int bn = blockIdx.x * BN;

    float acc[2][6][4];
    #pragma unroll
    for (int i = 0; i < 2; i++)
        #pragma unroll
        for (int j = 0; j < 6; j++)
            #pragma unroll
            for (int q = 0; q < 4; q++) acc[i][j][q] = 0.0f;

    gemm_core(A, B, bm, bn, HH, HH / BK,
              smem_raw, tiles_u, tid, lane, wm, wn, acc);

    #pragma unroll
    for (int mt = 0; mt < 2; mt++) {
        #pragma unroll
        for (int nt = 0; nt < 6; nt++) {
            int row = bm + wm + mt * 16 + (lane >> 2);
            int col = bn + wn + nt * 8 + (lane & 3) * 2;
            __half2 v0 = __floats2half2_rn(acc[mt][nt][0], acc[mt][nt][1]);
            __half2 v1 = __floats2half2_rn(acc[mt][nt][2], acc[mt][nt][3]);
            *(__half2*)(C + (size_t)row * G4 + col) = v0;
            *(__half2*)(C + (size_t)(row + 8) * G4 + col) = v1;
        }
    }
}

// ---------------- K6: per-step LSTM pointwise (fp16 half2 gate reads) ----------------
__global__ void lstm_point(int s) {
    int idx = blockIdx.x * blockDim.x + threadIdx.x;
    if (idx >= 2 * BH * HH) return;
    int dir = idx / (BH * HH);
    int r   = idx % (BH * HH);
    int n   = r / HH;
    int j   = r % HH;
    int t   = dir ? (TT - 1 - s) : s;

    const __half2* gp = (const __half2*)(g_gatesX + ((size_t)(n * TT + t)) * (2 * G4)
                                         + (size_t)dir * G4 + 4 * j);
    float2 p0 = __half22float2(gp[0]);
    float2 p1 = __half22float2(gp[1]);
    float gi = p0.x, gf = p0.y, gg = p1.x, go = p1.y;

    float c;
    if (s == 0) {
        c = sigf(gi) * tanhf(gg);
    } else {
        const __half2* tp = (const __half2*)(g_gtmp + (size_t)dir * BH * G4 + (size_t)n * G4 + 4 * j);
        float2 t0 = __half22float2(tp[0]);
        float2 t1 = __half22float2(tp[1]);
        gi += t0.x; gf += t0.y; gg += t1.x; go += t1.y;
        c = sigf(gf) * g_c[idx] + sigf(gi) * tanhf(gg);
    }
    float h = sigf(go) * tanhf(c);
    g_c[idx] = c;
    g_hb[idx] = __float2half(h);
    g_compose[((size_t)n * TT + t) * DMODEL + dir * HH + j] = h;
}

// ---------------- K7: logits_rep (parallelized, deep ILP) ----------------
__global__ void logits_rep_kernel(const float* __restrict__ logits, const int* __restrict__ mask) {
    int b = blockIdx.x;
    int d = blockIdx.y * 128 + threadIdx.x;
    int tid = threadIdx.x;

    __shared__ unsigned char repl[SEQ];
    for (int i = tid; i < SEQ; i += blockDim.x) repl[i] = 0;
    __syncthreads();
    if (tid < 2 * HEADS) {
        int h = tid >> 1, half = tid & 1;
        int st = window_start(g_master[(b * HEADS + h) * 2 + half]);
        int base = half * LHALF + st;
        for (int k = 0; k < TT; k++) repl[base + k] = 1;
    }
    __syncthreads();
    for (int sPos = tid; sPos < SEQ; sPos += blockDim.x)
        repl[sPos] = (repl[sPos] && mask[b * SEQ + sPos] == 0) ? 1 : 0;
    __syncthreads();

    float a0 = 0.f, a1 = 0.f, a2 = 0.f, a3 = 0.f;
    const float* lp = logits + (size_t)b * SEQ * DMODEL + d;
    for (int sPos = 0; sPos < SEQ; sPos += 8) {
        float v0 = __ldg(lp + (size_t)(sPos + 0) * DMODEL);
        float v1 = __ldg(lp + (size_t)(sPos + 1) * DMODEL);
        float v2 = __ldg(lp + (size_t)(sPos + 2) * DMODEL);
        float v3 = __ldg(lp + (size_t)(sPos + 3) * DMODEL);
        float v4 = __ldg(lp + (size_t)(sPos + 4) * DMODEL);
        float v5 = __ldg(lp + (size_t)(sPos + 5) * DMODEL);
        float v6 = __ldg(lp + (size_t)(sPos + 6) * DMODEL);
        float v7 = __ldg(lp + (size_t)(sPos + 7) * DMODEL);
        a0 += repl[sPos]     ? EPSV : v0;
        a1 += repl[sPos + 1] ? EPSV : v1;
        a2 += repl[sPos + 2] ? EPSV : v2;
        a3 += repl[sPos + 3] ? EPSV : v3;
        a0 += repl[sPos + 4] ? EPSV : v4;
        a1 += repl[sPos + 5] ? EPSV : v5;
        a2 += repl[sPos + 6] ? EPSV : v6;
        a3 += repl[sPos + 7] ? EPSV : v7;
    }
    g_lrep[(size_t)b * DMODEL + d] = (a0 + a1 + a2 + a3) * (1.0f / (float)SEQ);
}

// ---------------- K8: final FC + softmax ----------------
__global__ void final_kernel(const float* __restrict__ fcw, const float* __restrict__ fcb,
                             float* __restrict__ out) {
    int b = blockIdx.x;
    int tid = threadIdx.x;
    const int NF = DMODEL * (HEADS + 1);
    float a0 = 0.0f, a1 = 0.0f;

    for (int j = tid; j < NF; j += 256) {
        float x;
        if (j < HEADS * DMODEL) {
            int h = j / DMODEL, d = j % DMODEL;
            int n = b * HEADS + h;
            const float* cp = g_compose + (size_t)n * TT * DMODEL + d;
            float s = 0.0f;
            #pragma unroll
            for (int t = 0; t < TT; t++) s += cp[(size_t)t * DMODEL];
            x = s * (1.0f / (float)TT);
        } else {
            x = g_lrep[(size_t)b * DMODEL + (j - HEADS * DMODEL)];
        }
        a0 += x * fcw[j];
        a1 += x * fcw[NF + j];
    }

    __shared__ float s0[256], s1[256];
    s0[tid] = a0; s1[tid] = a1;
    __syncthreads();
    for (int off = 128; off > 0; off >>= 1) {
        if (tid < off) { s0[tid] += s0[tid + off]; s1[tid] += s1[tid + off]; }
        __syncthreads();
    }
    if (tid == 0) {
        float l0 = s0[0] + fcb[0], l1 = s1[0] + fcb[1];
        float m = fmaxf(l0, l1);
        float e0 = expf(l0 - m), e1 = expf(l1 - m);
        float inv = 1.0f / (e0 + e1);
        out[b * 2 + 0] = e0 * inv;
        out[b * 2 + 1] = e1 * inv;
    }
}

// ---------------- launch ----------------
extern "C" void kernel_launch(void* const* d_in, const int* in_sizes, int n_in,
                              void* d_out, int out_size) {
    const int*   sents = (const int*)d_in[0];
    const float* att   = (const float*)d_in[1];
    const float* logits= (const float*)d_in[2];
    const int*   mask  = (const int*)d_in[3];
    const float* wih_f = (const float*)d_in[4];
    const float* whh_f = (const float*)d_in[5];
    const float* bih_f = (const float*)d_in[6];
    const float* bhh_f = (const float*)d_in[7];
    const float* wih_r = (const float*)d_in[8];
    const float* whh_r = (const float*)d_in[9];
    const float* bih_r = (const float*)d_in[10];
    const float* bhh_r = (const float*)d_in[11];
    const float* fc_w  = (const float*)d_in[12];
    const float* fc_b  = (const float*)d_in[13];
    float* out = (float*)d_out;

    cudaFuncSetAttribute(input_gemm_hmma, cudaFuncAttributeMaxDynamicSharedMemorySize, GM_SMEM);
    cudaFuncSetAttribute(rec_gemm_hmma, cudaFuncAttributeMaxDynamicSharedMemorySize, GM_SMEM);

    prep_kernel<<<(int)((PREP_TOTAL + 255) / 256), 256>>>(wih_f, wih_r, whh_f, whh_r,
                                                          bih_f, bhh_f, bih_r, bhh_r);
    masters_kernel<<<BH * 2, 256>>>(att, sents);
    build_slide<<<BH, 256>>>(logits, mask);

    // input GEMM: gatesX(2304x3072) = slide @ Wperm^T + bias
    input_gemm_hmma<<<dim3(2 * G4 / BN, BH * TT / 64), 256, GM_SMEM>>>();

    for (int s = 0; s < TT; s++) {
        lstm_point<<<(2 * BH * HH + 255) / 256, 256>>>(s);
        if (s < TT - 1) {
            rec_gemm_hmma<<<dim3(G4 / BN, BH / 64, 2), 256, GM_SMEM>>>();
        }
    }

    logits_rep_kernel<<<dim3(BATCH, DMODEL / 128), 128>>>(logits, mask);
    final_kernel<<<BATCH, 256>>>(fc_w, fc_b, out);
}